// round 4
// baseline (speedup 1.0000x reference)
#include <cuda_runtime.h>
#include <cuda_bf16.h>
#include <math.h>
#include <stdint.h>

#define BB 2
#define TT 8192
#define CC 1024
#define HH 16
#define DD 64
#define MTOT (BB*TT)        // 16384
#define QKVC (3*CC)         // 3072

// quantization scales (fixed, conservative vs. N(0,1)/N(0,1/1024) maxima)
#define SX  6.5f
#define SWQ 0.2f
#define SO  7.0f
#define SWO 0.2f

// ---------------- device scratch ----------------
__device__ float g_qkv[(size_t)MTOT * QKVC];       // 192 MB fp32
__device__ int8_t g_x1[(size_t)MTOT * CC];
__device__ int8_t g_x2[(size_t)MTOT * CC];
__device__ int8_t g_o1[(size_t)MTOT * CC];         // scrambled attn out, 2-level int8
__device__ int8_t g_o2[(size_t)MTOT * CC];
__device__ int8_t g_wq1[(size_t)QKVC * CC];
__device__ int8_t g_wq2[(size_t)QKVC * CC];
__device__ int8_t g_wo1[(size_t)CC * CC];
__device__ int8_t g_wo2[(size_t)CC * CC];
__device__ float g_cos[TT * 32];
__device__ float g_sin[TT * 32];

// ---------------- PTX helpers (compute_103 baseline) ----------------
__device__ __forceinline__ uint32_t smem_u32(const void* p) {
    uint32_t a;
    asm("{ .reg .u64 t; cvta.to.shared.u64 t, %1; cvt.u32.u64 %0, t; }" : "=r"(a) : "l"(p));
    return a;
}
__device__ __forceinline__ void cp16(uint32_t s, const void* g) {
    asm volatile("cp.async.cg.shared.global [%0], [%1], 16;" :: "r"(s), "l"(g));
}
#define CP_COMMIT() asm volatile("cp.async.commit_group;" ::: "memory")
#define CP_WAIT(n)  asm volatile("cp.async.wait_group %0;" :: "n"(n) : "memory")

__device__ __forceinline__ void ldsm_x4(uint32_t* r, uint32_t addr) {
    asm volatile("ldmatrix.sync.aligned.m8n8.x4.shared.b16 {%0,%1,%2,%3}, [%4];"
                 : "=r"(r[0]), "=r"(r[1]), "=r"(r[2]), "=r"(r[3]) : "r"(addr));
}
// int8 MMA: D(s32) += A(s8,16x32) * B(s8,8x32)^T
#define MMA_S8(d, a, b0, b1) \
    asm volatile("mma.sync.aligned.m16n8k32.row.col.s32.s8.s8.s32 " \
                 "{%0,%1,%2,%3}, {%4,%5,%6,%7}, {%8,%9}, {%0,%1,%2,%3};" \
                 : "+r"((d)[0]), "+r"((d)[1]), "+r"((d)[2]), "+r"((d)[3]) \
                 : "r"((a)[0]), "r"((a)[1]), "r"((a)[2]), "r"((a)[3]), \
                   "r"(b0), "r"(b1))

// ---------------- small kernels ----------------
__global__ void rope_table_kernel() {
    int idx = blockIdx.x * blockDim.x + threadIdx.x;
    if (idx >= TT * 32) return;
    int t = idx >> 5, d2 = idx & 31;
    float invf = (float)pow(10000.0, -(double)d2 / 32.0);
    float ang = __fmul_rn((float)t, invf);
    g_cos[idx] = (float)cos((double)ang);
    g_sin[idx] = (float)sin((double)ang);
}

// fp32 -> two-level int8: v ~= s1*(q1 + q2/127)
__device__ __forceinline__ void quant2(float v, float s1, float inv_s1, int8_t& q1, int8_t& q2) {
    float a1 = rintf(v * inv_s1);
    a1 = fminf(fmaxf(a1, -127.f), 127.f);
    float r = v - a1 * s1;
    float a2 = rintf(r * inv_s1 * 127.f);
    a2 = fminf(fmaxf(a2, -127.f), 127.f);
    q1 = (int8_t)(int)a1;
    q2 = (int8_t)(int)a2;
}

__global__ void quant_kernel(const float4* __restrict__ in,
                             char4* __restrict__ q1, char4* __restrict__ q2,
                             int n4, float s1, float inv_s1) {
    int i = blockIdx.x * blockDim.x + threadIdx.x;
    if (i >= n4) return;
    float4 v = in[i];
    int8_t a,b,c,d, e,f,g,h;
    quant2(v.x, s1, inv_s1, a, e);
    quant2(v.y, s1, inv_s1, b, f);
    quant2(v.z, s1, inv_s1, c, g);
    quant2(v.w, s1, inv_s1, d, h);
    char4 hi; hi.x=a; hi.y=b; hi.z=c; hi.w=d;
    char4 lo; lo.x=e; lo.y=f; lo.z=g; lo.w=h;
    q1[i] = hi; q2[i] = lo;
}

// ---------------- int8 IMMA GEMM (NT): C[m,n] = sum_k A[m,k]*B[n,k] ----------------
// 3-term 2-level int8: a1b1 (acc_m) + a1b2 + a2b1 (acc_c, shared scale).
// C = C1*acc_m + (C1/127)*acc_c.   Tile 128x128, BK=128 (128B rows), 3-stage cp.async.
#define BM 128
#define BN 128
#define BKQ 128
#define T_A1 0
#define T_A2 (16*1024)
#define T_B1 (32*1024)
#define T_B2 (48*1024)
#define STG  (64*1024)
#define NSTAGE 3
#define GEMM_DYN (NSTAGE*STG + 1024)

extern __shared__ char dynsmem[];

__global__ __launch_bounds__(256, 1) void gemm_imma(
    const int8_t* __restrict__ A1, const int8_t* __restrict__ A2,
    const int8_t* __restrict__ B1, const int8_t* __restrict__ B2,
    float* __restrict__ C, int ldc, int K, float C1, float C2)
{
    const int tid  = threadIdx.x;
    const int wid  = tid >> 5;
    const int lane = tid & 31;
    const int m0 = blockIdx.y * BM;
    const int n0 = blockIdx.x * BN;
    const int wm = (wid >> 1) * 32;   // warp m offset
    const int wn = (wid & 1) * 64;    // warp n offset

    uint32_t sbase = (smem_u32(dynsmem) + 1023u) & ~1023u;

    // ---- loaders: thread -> row tid/2, 4 x 16B chunks per tensor ----
    const int lrow = tid >> 1;
    const int lc4  = (tid & 1) * 4;   // chunk index (of 8 per 128B row)
    uint32_t soff[4];
#pragma unroll
    for (int c = 0; c < 4; ++c) {
        uint32_t off = (uint32_t)lrow * 128 + (uint32_t)(lc4 + c) * 16;
        soff[c] = off ^ ((off >> 3) & 0x70);
    }
    const int8_t* gA1 = A1 + (size_t)(m0 + lrow) * K + lc4 * 16;
    const int8_t* gA2 = A2 + (size_t)(m0 + lrow) * K + lc4 * 16;
    const int8_t* gB1 = B1 + (size_t)(n0 + lrow) * K + lc4 * 16;
    const int8_t* gB2 = B2 + (size_t)(n0 + lrow) * K + lc4 * 16;

    auto load_stage = [&](int stage, int iter) {
        uint32_t st = sbase + (uint32_t)stage * STG;
        const int k0 = iter * BKQ;
#pragma unroll
        for (int c = 0; c < 4; ++c) {
            cp16(st + T_A1 + soff[c], gA1 + k0 + c * 16);
            cp16(st + T_A2 + soff[c], gA2 + k0 + c * 16);
            cp16(st + T_B1 + soff[c], gB1 + k0 + c * 16);
            cp16(st + T_B2 + soff[c], gB2 + k0 + c * 16);
        }
        CP_COMMIT();
    };

    // ---- ldmatrix address precompute (identical byte layout to bf16 k16 case) ----
    uint32_t a_rt[2], a_xr[2];
#pragma unroll
    for (int ti = 0; ti < 2; ++ti) {
        int r = wm + ti * 16 + (lane & 15);
        a_rt[ti] = (uint32_t)r * 128;
        a_xr[ti] = (uint32_t)(r & 7) << 4;
    }
    const uint32_t a_cb = (uint32_t)(lane >> 4) * 16;
    uint32_t b_rt[4], b_xr[4];
#pragma unroll
    for (int ni = 0; ni < 4; ++ni) {
        int r = wn + ni * 16 + (lane & 7) + (lane >> 4) * 8;
        b_rt[ni] = (uint32_t)r * 128;
        b_xr[ni] = (uint32_t)(r & 7) << 4;
    }
    const uint32_t b_cb = (uint32_t)((lane >> 3) & 1) * 16;

    int32_t accm[2][8][4];   // a1*b1
    int32_t accc[2][8][4];   // a1*b2 + a2*b1 (shared scale)
#pragma unroll
    for (int i = 0; i < 2; ++i)
#pragma unroll
        for (int j = 0; j < 8; ++j)
#pragma unroll
            for (int q = 0; q < 4; ++q) { accm[i][j][q] = 0; accc[i][j][q] = 0; }

    const int niter = K / BKQ;   // 8

#pragma unroll
    for (int s = 0; s < NSTAGE - 1; ++s) load_stage(s, s);

    for (int i = 0; i < niter; ++i) {
        if (i + NSTAGE - 1 < niter) { CP_WAIT(1); } else { CP_WAIT(0); }
        __syncthreads();
        if (i + NSTAGE - 1 < niter) load_stage((i + NSTAGE - 1) % NSTAGE, i + NSTAGE - 1);

        uint32_t base = sbase + (uint32_t)(i % NSTAGE) * STG;
#pragma unroll
        for (int ks = 0; ks < 4; ++ks) {                // 4 x k32 per 128B row
            const uint32_t kb = (uint32_t)ks * 32;
            uint32_t a1[2][4], a2[2][4], b1[4][4], b2[4][4];
#pragma unroll
            for (int ti = 0; ti < 2; ++ti) {
                uint32_t col = (a_cb + kb) ^ a_xr[ti];
                ldsm_x4(a1[ti], base + T_A1 + a_rt[ti] + col);
                ldsm_x4(a2[ti], base + T_A2 + a_rt[ti] + col);
            }
#pragma unroll
            for (int ni = 0; ni < 4; ++ni) {
                uint32_t col = (b_cb + kb) ^ b_xr[ni];
                ldsm_x4(b1[ni], base + T_B1 + b_rt[ni] + col);
                ldsm_x4(b2[ni], base + T_B2 + b_rt[ni] + col);
            }
#pragma unroll
            for (int mi = 0; mi < 2; ++mi)
#pragma unroll
                for (int ni = 0; ni < 4; ++ni) {
                    MMA_S8(accm[mi][2*ni],   a1[mi], b1[ni][0], b1[ni][1]);
                    MMA_S8(accm[mi][2*ni+1], a1[mi], b1[ni][2], b1[ni][3]);
                    MMA_S8(accc[mi][2*ni],   a1[mi], b2[ni][0], b2[ni][1]);
                    MMA_S8(accc[mi][2*ni+1], a1[mi], b2[ni][2], b2[ni][3]);
                    MMA_S8(accc[mi][2*ni],   a2[mi], b1[ni][0], b1[ni][1]);
                    MMA_S8(accc[mi][2*ni+1], a2[mi], b1[ni][2], b1[ni][3]);
                }
        }
        __syncthreads();
    }

    // ---- epilogue ----
#pragma unroll
    for (int mi = 0; mi < 2; ++mi) {
        int gm = m0 + wm + mi * 16 + (lane >> 2);
#pragma unroll
        for (int ni = 0; ni < 8; ++ni) {
            int gn = n0 + wn + ni * 8 + (lane & 3) * 2;
            float2 v0, v1;
            v0.x = C1 * (float)accm[mi][ni][0] + C2 * (float)accc[mi][ni][0];
            v0.y = C1 * (float)accm[mi][ni][1] + C2 * (float)accc[mi][ni][1];
            v1.x = C1 * (float)accm[mi][ni][2] + C2 * (float)accc[mi][ni][2];
            v1.y = C1 * (float)accm[mi][ni][3] + C2 * (float)accc[mi][ni][3];
            *(float2*)(C + (size_t)gm * ldc + gn) = v0;
            *(float2*)(C + (size_t)(gm + 8) * ldc + gn) = v1;
        }
    }
}

// ---------------- fused RoPE + per-token 16x16 head-attn + scrambled int8 quant ----------------
#define PAD 65
__global__ __launch_bounds__(256) void attn_kernel()
{
    __shared__ float q [HH][PAD];
    __shared__ float kk[HH][PAD];
    __shared__ float vv[HH][PAD];
    __shared__ float sc[HH][17];
    __shared__ float cs[32], sn[32];

    const int tok = blockIdx.x;
    const int b = tok >> 13;
    const int t = tok & (TT - 1);
    const int tid = threadIdx.x;

    if (tid < 32) { cs[tid] = g_cos[t*32 + tid]; sn[tid] = g_sin[t*32 + tid]; }

    const float* row = g_qkv + (size_t)tok * QKVC;
#pragma unroll
    for (int r = 0; r < 12; ++r) {
        int idx = tid + 256 * r;
        float val = row[idx];
        int s = idx >> 10;
        int h = (idx >> 6) & 15;
        int d = idx & 63;
        if      (s == 0) q [h][d] = val;
        else if (s == 1) kk[h][d] = val;
        else             vv[h][d] = val;
    }
    __syncthreads();

#pragma unroll
    for (int r = 0; r < 4; ++r) {
        int idx = tid + 256 * r;
        int which = idx >> 9;
        int h = (idx >> 5) & 15;
        int d2 = idx & 31;
        float c = cs[d2], s = sn[d2];
        float* buf = which ? &kk[0][0] : &q[0][0];
        float x1 = buf[h*PAD + 2*d2];
        float x2 = buf[h*PAD + 2*d2 + 1];
        buf[h*PAD + 2*d2]     = x1*c - x2*s;
        buf[h*PAD + 2*d2 + 1] = x2*c + x1*s;
    }
    __syncthreads();

    {
        int hq = tid >> 4, hk = tid & 15;
        float s = 0.f;
#pragma unroll
        for (int d = 0; d < DD; ++d) s = fmaf(q[hq][d], kk[hk][d], s);
        sc[hq][hk] = s * 0.125f;
    }
    __syncthreads();

    if (tid < 16) {
        float mx = -1e30f;
#pragma unroll
        for (int j = 0; j < 16; ++j) mx = fmaxf(mx, sc[tid][j]);
        float sum = 0.f;
#pragma unroll
        for (int j = 0; j < 16; ++j) { float e = expf(sc[tid][j] - mx); sc[tid][j] = e; sum += e; }
        float inv = 1.f / sum;
#pragma unroll
        for (int j = 0; j < 16; ++j) sc[tid][j] *= inv;
    }
    __syncthreads();

    const float s1o = SO / 127.f, inv_s1o = 127.f / SO;
    const size_t obase = ((size_t)b * TT + (t >> 4)) * (size_t)CC + (size_t)(t & 15) * DD;
#pragma unroll
    for (int r = 0; r < 4; ++r) {
        int idx = tid + 256 * r;
        int hq = idx >> 6, d = idx & 63;
        float o = 0.f;
#pragma unroll
        for (int hk = 0; hk < 16; ++hk) o = fmaf(sc[hq][hk], vv[hk][d], o);
        size_t oi = obase + (size_t)hq * 512 * CC + d;
        int8_t q1, q2;
        quant2(o, s1o, inv_s1o, q1, q2);
        g_o1[oi] = q1;
        g_o2[oi] = q2;
    }
}

// ---------------------------------------------------------------------------
extern "C" void kernel_launch(void* const* d_in, const int* in_sizes, int n_in,
                              void* d_out, int out_size)
{
    const float* x    = (const float*)d_in[0];
    const float* Wqkv = (const float*)d_in[1];
    const float* Wout = (const float*)d_in[2];
    float* out = (float*)d_out;

    float* qkv_p;
    int8_t *x1,*x2,*o1,*o2,*wq1,*wq2,*wo1,*wo2;
    cudaGetSymbolAddress((void**)&qkv_p, g_qkv);
    cudaGetSymbolAddress((void**)&x1, g_x1);   cudaGetSymbolAddress((void**)&x2, g_x2);
    cudaGetSymbolAddress((void**)&o1, g_o1);   cudaGetSymbolAddress((void**)&o2, g_o2);
    cudaGetSymbolAddress((void**)&wq1, g_wq1); cudaGetSymbolAddress((void**)&wq2, g_wq2);
    cudaGetSymbolAddress((void**)&wo1, g_wo1); cudaGetSymbolAddress((void**)&wo2, g_wo2);

    cudaFuncSetAttribute(gemm_imma, cudaFuncAttributeMaxDynamicSharedMemorySize, GEMM_DYN);

    rope_table_kernel<<<(TT*32 + 255) / 256, 256>>>();
    quant_kernel<<<(MTOT*CC/4 + 255) / 256, 256>>>((const float4*)x,    (char4*)x1,  (char4*)x2,  MTOT*CC/4, SX/127.f,  127.f/SX);
    quant_kernel<<<(QKVC*CC/4 + 255) / 256, 256>>>((const float4*)Wqkv, (char4*)wq1, (char4*)wq2, QKVC*CC/4, SWQ/127.f, 127.f/SWQ);
    quant_kernel<<<(CC*CC/4   + 255) / 256, 256>>>((const float4*)Wout, (char4*)wo1, (char4*)wo2, CC*CC/4,   SWO/127.f, 127.f/SWO);

    // GEMM1: qkv = x @ Wqkv^T  (M=16384, N=3072, K=1024)
    {
        const float c1 = (SX/127.f) * (SWQ/127.f);
        dim3 grid(QKVC / BN, MTOT / BM);
        gemm_imma<<<grid, 256, GEMM_DYN>>>(x1, x2, wq1, wq2, qkv_p, QKVC, CC, c1, c1/127.f);
    }

    // fused RoPE + head-attention + scramble + int8 quant
    attn_kernel<<<MTOT, 256>>>();

    // GEMM2: out = scr @ Wout^T (M=16384, N=1024, K=1024)
    {
        const float c1 = (SO/127.f) * (SWO/127.f);
        dim3 grid(CC / BN, MTOT / BM);
        gemm_imma<<<grid, 256, GEMM_DYN>>>(o1, o2, wo1, wo2, out, CC, CC, c1, c1/127.f);
    }
}

// round 5
// speedup vs baseline: 2.1065x; 2.1065x over previous
#include <cuda_runtime.h>
#include <cuda_bf16.h>
#include <math.h>
#include <stdint.h>

#define BB 2
#define TT 8192
#define CC 1024
#define HH 16
#define DD 64
#define MTOT (BB*TT)        // 16384
#define QKVC (3*CC)         // 3072

// ---------------- device scratch ----------------
__device__ float g_qkv[(size_t)MTOT * QKVC];                 // 192 MB fp32
__device__ __nv_bfloat16 g_xh[(size_t)MTOT * CC];
__device__ __nv_bfloat16 g_xl[(size_t)MTOT * CC];
__device__ __nv_bfloat16 g_sh[(size_t)MTOT * CC];
__device__ __nv_bfloat16 g_sl[(size_t)MTOT * CC];
__device__ __nv_bfloat16 g_wqh[(size_t)QKVC * CC];
__device__ __nv_bfloat16 g_wql[(size_t)QKVC * CC];
__device__ __nv_bfloat16 g_woh[(size_t)CC * CC];
__device__ __nv_bfloat16 g_wol[(size_t)CC * CC];
__device__ float g_cos[TT * 32];
__device__ float g_sin[TT * 32];

// ---------------- PTX helpers (compute_103-baseline only) ----------------
__device__ __forceinline__ uint32_t smem_u32(const void* p) {
    uint32_t a;
    asm("{ .reg .u64 t; cvta.to.shared.u64 t, %1; cvt.u32.u64 %0, t; }" : "=r"(a) : "l"(p));
    return a;
}
__device__ __forceinline__ void cp16(uint32_t s, const void* g) {
    asm volatile("cp.async.cg.shared.global [%0], [%1], 16;" :: "r"(s), "l"(g));
}
#define CP_COMMIT() asm volatile("cp.async.commit_group;" ::: "memory")
#define CP_WAIT(n)  asm volatile("cp.async.wait_group %0;" :: "n"(n) : "memory")

__device__ __forceinline__ void ldsm_x4(uint32_t* r, uint32_t addr) {
    asm volatile("ldmatrix.sync.aligned.m8n8.x4.shared.b16 {%0,%1,%2,%3}, [%4];"
                 : "=r"(r[0]), "=r"(r[1]), "=r"(r[2]), "=r"(r[3]) : "r"(addr));
}
#define MMA_BF16(d, a, b0, b1) \
    asm volatile("mma.sync.aligned.m16n8k16.row.col.f32.bf16.bf16.f32 " \
                 "{%0,%1,%2,%3}, {%4,%5,%6,%7}, {%8,%9}, {%0,%1,%2,%3};" \
                 : "+f"((d)[0]), "+f"((d)[1]), "+f"((d)[2]), "+f"((d)[3]) \
                 : "r"((a)[0]), "r"((a)[1]), "r"((a)[2]), "r"((a)[3]), \
                   "r"(b0), "r"(b1))

// ---------------- small kernels ----------------
__global__ void rope_table_kernel() {
    int idx = blockIdx.x * blockDim.x + threadIdx.x;
    if (idx >= TT * 32) return;
    int t = idx >> 5, d2 = idx & 31;
    float invf = (float)pow(10000.0, -(double)d2 / 32.0);
    float ang = __fmul_rn((float)t, invf);
    g_cos[idx] = (float)cos((double)ang);
    g_sin[idx] = (float)sin((double)ang);
}

__global__ void split_kernel(const float4* __restrict__ in,
                             __nv_bfloat162* __restrict__ hi,
                             __nv_bfloat162* __restrict__ lo, int n4) {
    int i = blockIdx.x * blockDim.x + threadIdx.x;
    if (i >= n4) return;
    float4 v = in[i];
    __nv_bfloat16 h0 = __float2bfloat16(v.x), h1 = __float2bfloat16(v.y);
    __nv_bfloat16 h2 = __float2bfloat16(v.z), h3 = __float2bfloat16(v.w);
    __nv_bfloat162 H0; H0.x = h0; H0.y = h1;
    __nv_bfloat162 H1; H1.x = h2; H1.y = h3;
    __nv_bfloat162 L0; L0.x = __float2bfloat16(v.x - __bfloat162float(h0));
                       L0.y = __float2bfloat16(v.y - __bfloat162float(h1));
    __nv_bfloat162 L1; L1.x = __float2bfloat16(v.z - __bfloat162float(h2));
                       L1.y = __float2bfloat16(v.w - __bfloat162float(h3));
    hi[2*i] = H0; hi[2*i+1] = H1;
    lo[2*i] = L0; lo[2*i+1] = L1;
}

// ---------------- mma.sync GEMM (NT): C[m,n] = sum_k A[m,k]*B[n,k] ----------------
// bf16x3 split: Ah*Bh + Al*Bh + Ah*Bl, fp32 accum.
// 128x128 tile, BK=64, 3-stage cp.async pipeline, SW128 swizzle.
// MMA stream is term-major so same-accumulator reuse distance is 16 instrs.
#define BM 128
#define BN 128
#define BKQ 64
#define T_AH 0
#define T_AL (16*1024)
#define T_BH (32*1024)
#define T_BL (48*1024)
#define STG  (64*1024)
#define NSTAGE 3
#define GEMM_DYN (NSTAGE*STG + 1024)

extern __shared__ char dynsmem[];

__global__ __launch_bounds__(256, 1) void gemm_mma(
    const __nv_bfloat16* __restrict__ Ah, const __nv_bfloat16* __restrict__ Al,
    const __nv_bfloat16* __restrict__ Bh, const __nv_bfloat16* __restrict__ Bl,
    float* __restrict__ C, int ldc, int K)
{
    const int tid  = threadIdx.x;
    const int wid  = tid >> 5;
    const int lane = tid & 31;
    const int m0 = blockIdx.y * BM;
    const int n0 = blockIdx.x * BN;
    const int wm = (wid >> 1) * 32;   // warp m offset in tile
    const int wn = (wid & 1) * 64;    // warp n offset in tile

    uint32_t sbase = (smem_u32(dynsmem) + 1023u) & ~1023u;

    // ---- loader setup ----
    const int lrow = tid >> 1;
    const int lc4  = (tid & 1) * 4;
    uint32_t soff[4];
#pragma unroll
    for (int c = 0; c < 4; ++c) {
        uint32_t off = (uint32_t)lrow * 128 + (uint32_t)(lc4 + c) * 16;
        soff[c] = off ^ ((off >> 3) & 0x70);
    }
    const __nv_bfloat16* gAh = Ah + (size_t)(m0 + lrow) * K + lc4 * 8;
    const __nv_bfloat16* gAl = Al + (size_t)(m0 + lrow) * K + lc4 * 8;
    const __nv_bfloat16* gBh = Bh + (size_t)(n0 + lrow) * K + lc4 * 8;
    const __nv_bfloat16* gBl = Bl + (size_t)(n0 + lrow) * K + lc4 * 8;

    auto load_stage = [&](int stage, int iter) {
        uint32_t st = sbase + (uint32_t)stage * STG;
        const int k0 = iter * BKQ;
#pragma unroll
        for (int c = 0; c < 4; ++c) {
            cp16(st + T_AH + soff[c], gAh + k0 + c * 8);
            cp16(st + T_AL + soff[c], gAl + k0 + c * 8);
            cp16(st + T_BH + soff[c], gBh + k0 + c * 8);
            cp16(st + T_BL + soff[c], gBl + k0 + c * 8);
        }
        CP_COMMIT();
    };

    // ---- ldmatrix address precompute ----
    uint32_t a_rt[2], a_xr[2];
#pragma unroll
    for (int ti = 0; ti < 2; ++ti) {
        int r = wm + ti * 16 + (lane & 15);
        a_rt[ti] = (uint32_t)r * 128;
        a_xr[ti] = (uint32_t)(r & 7) << 4;
    }
    const uint32_t a_cb = (uint32_t)(lane >> 4) * 16;
    uint32_t b_rt[4], b_xr[4];
#pragma unroll
    for (int ni = 0; ni < 4; ++ni) {
        int r = wn + ni * 16 + (lane & 7) + (lane >> 4) * 8;
        b_rt[ni] = (uint32_t)r * 128;
        b_xr[ni] = (uint32_t)(r & 7) << 4;
    }
    const uint32_t b_cb = (uint32_t)((lane >> 3) & 1) * 16;

    float acc[2][8][4];
#pragma unroll
    for (int i = 0; i < 2; ++i)
#pragma unroll
        for (int j = 0; j < 8; ++j)
#pragma unroll
            for (int q = 0; q < 4; ++q) acc[i][j][q] = 0.f;

    const int niter = K / BKQ;   // 16

#pragma unroll
    for (int s = 0; s < NSTAGE - 1; ++s) load_stage(s, s);

    for (int i = 0; i < niter; ++i) {
        if (i + NSTAGE - 1 < niter) { CP_WAIT(1); } else { CP_WAIT(0); }
        __syncthreads();
        if (i + NSTAGE - 1 < niter) load_stage((i + NSTAGE - 1) % NSTAGE, i + NSTAGE - 1);

        uint32_t base = sbase + (uint32_t)(i % NSTAGE) * STG;
#pragma unroll
        for (int ks = 0; ks < 4; ++ks) {
            const uint32_t kb = (uint32_t)ks * 32;
            uint32_t ah[2][4], al[2][4], bh[4][4], bl[4][4];
            // hh-operands first so hh MMAs can start while al/bl loads drain
#pragma unroll
            for (int ti = 0; ti < 2; ++ti)
                ldsm_x4(ah[ti], base + T_AH + a_rt[ti] + ((a_cb + kb) ^ a_xr[ti]));
#pragma unroll
            for (int ni = 0; ni < 4; ++ni)
                ldsm_x4(bh[ni], base + T_BH + b_rt[ni] + ((b_cb + kb) ^ b_xr[ni]));
#pragma unroll
            for (int ti = 0; ti < 2; ++ti)
                ldsm_x4(al[ti], base + T_AL + a_rt[ti] + ((a_cb + kb) ^ a_xr[ti]));
#pragma unroll
            for (int ni = 0; ni < 4; ++ni)
                ldsm_x4(bl[ni], base + T_BL + b_rt[ni] + ((b_cb + kb) ^ b_xr[ni]));

            // term-major MMA stream: all 16 accumulators touched per term
#pragma unroll
            for (int mi = 0; mi < 2; ++mi)
#pragma unroll
                for (int ni = 0; ni < 4; ++ni) {
                    MMA_BF16(acc[mi][2*ni],   ah[mi], bh[ni][0], bh[ni][1]);
                    MMA_BF16(acc[mi][2*ni+1], ah[mi], bh[ni][2], bh[ni][3]);
                }
#pragma unroll
            for (int mi = 0; mi < 2; ++mi)
#pragma unroll
                for (int ni = 0; ni < 4; ++ni) {
                    MMA_BF16(acc[mi][2*ni],   al[mi], bh[ni][0], bh[ni][1]);
                    MMA_BF16(acc[mi][2*ni+1], al[mi], bh[ni][2], bh[ni][3]);
                }
#pragma unroll
            for (int mi = 0; mi < 2; ++mi)
#pragma unroll
                for (int ni = 0; ni < 4; ++ni) {
                    MMA_BF16(acc[mi][2*ni],   ah[mi], bl[ni][0], bl[ni][1]);
                    MMA_BF16(acc[mi][2*ni+1], ah[mi], bl[ni][2], bl[ni][3]);
                }
        }
        __syncthreads();
    }

    // ---- epilogue ----
#pragma unroll
    for (int mi = 0; mi < 2; ++mi) {
        int gm = m0 + wm + mi * 16 + (lane >> 2);
#pragma unroll
        for (int ni = 0; ni < 8; ++ni) {
            int gn = n0 + wn + ni * 8 + (lane & 3) * 2;
            float2 v0 = make_float2(acc[mi][ni][0], acc[mi][ni][1]);
            float2 v1 = make_float2(acc[mi][ni][2], acc[mi][ni][3]);
            *(float2*)(C + (size_t)gm * ldc + gn) = v0;
            *(float2*)(C + (size_t)(gm + 8) * ldc + gn) = v1;
        }
    }
}

// ---------------- fused RoPE + per-token 16x16 head-attn + scrambled bf16 split ----------------
#define PAD 65
__global__ __launch_bounds__(256) void attn_kernel()
{
    __shared__ float q [HH][PAD];
    __shared__ float kk[HH][PAD];
    __shared__ float vv[HH][PAD];
    __shared__ float sc[HH][17];
    __shared__ float cs[32], sn[32];

    const int tok = blockIdx.x;
    const int b = tok >> 13;
    const int t = tok & (TT - 1);
    const int tid = threadIdx.x;

    if (tid < 32) { cs[tid] = g_cos[t*32 + tid]; sn[tid] = g_sin[t*32 + tid]; }

    const float* row = g_qkv + (size_t)tok * QKVC;
#pragma unroll
    for (int r = 0; r < 12; ++r) {
        int idx = tid + 256 * r;
        float val = row[idx];
        int s = idx >> 10;
        int h = (idx >> 6) & 15;
        int d = idx & 63;
        if      (s == 0) q [h][d] = val;
        else if (s == 1) kk[h][d] = val;
        else             vv[h][d] = val;
    }
    __syncthreads();

#pragma unroll
    for (int r = 0; r < 4; ++r) {
        int idx = tid + 256 * r;
        int which = idx >> 9;
        int h = (idx >> 5) & 15;
        int d2 = idx & 31;
        float c = cs[d2], s = sn[d2];
        float* buf = which ? &kk[0][0] : &q[0][0];
        float x1 = buf[h*PAD + 2*d2];
        float x2 = buf[h*PAD + 2*d2 + 1];
        buf[h*PAD + 2*d2]     = x1*c - x2*s;
        buf[h*PAD + 2*d2 + 1] = x2*c + x1*s;
    }
    __syncthreads();

    {
        int hq = tid >> 4, hk = tid & 15;
        float s = 0.f;
#pragma unroll
        for (int d = 0; d < DD; ++d) s = fmaf(q[hq][d], kk[hk][d], s);
        sc[hq][hk] = s * 0.125f;
    }
    __syncthreads();

    if (tid < 16) {
        float mx = -1e30f;
#pragma unroll
        for (int j = 0; j < 16; ++j) mx = fmaxf(mx, sc[tid][j]);
        float sum = 0.f;
#pragma unroll
        for (int j = 0; j < 16; ++j) { float e = expf(sc[tid][j] - mx); sc[tid][j] = e; sum += e; }
        float inv = 1.f / sum;
#pragma unroll
        for (int j = 0; j < 16; ++j) sc[tid][j] *= inv;
    }
    __syncthreads();

    const size_t obase = ((size_t)b * TT + (t >> 4)) * (size_t)CC + (size_t)(t & 15) * DD;
#pragma unroll
    for (int r = 0; r < 4; ++r) {
        int idx = tid + 256 * r;
        int hq = idx >> 6, d = idx & 63;
        float o = 0.f;
#pragma unroll
        for (int hk = 0; hk < 16; ++hk) o = fmaf(sc[hq][hk], vv[hk][d], o);
        size_t oi = obase + (size_t)hq * 512 * CC + d;
        __nv_bfloat16 h = __float2bfloat16(o);
        g_sh[oi] = h;
        g_sl[oi] = __float2bfloat16(o - __bfloat162float(h));
    }
}

// ---------------------------------------------------------------------------
extern "C" void kernel_launch(void* const* d_in, const int* in_sizes, int n_in,
                              void* d_out, int out_size)
{
    const float* x    = (const float*)d_in[0];
    const float* Wqkv = (const float*)d_in[1];
    const float* Wout = (const float*)d_in[2];
    float* out = (float*)d_out;

    float *qkv_p;
    __nv_bfloat16 *xh, *xl, *sh, *sl, *wqh, *wql, *woh, *wol;
    cudaGetSymbolAddress((void**)&qkv_p, g_qkv);
    cudaGetSymbolAddress((void**)&xh, g_xh);   cudaGetSymbolAddress((void**)&xl, g_xl);
    cudaGetSymbolAddress((void**)&sh, g_sh);   cudaGetSymbolAddress((void**)&sl, g_sl);
    cudaGetSymbolAddress((void**)&wqh, g_wqh); cudaGetSymbolAddress((void**)&wql, g_wql);
    cudaGetSymbolAddress((void**)&woh, g_woh); cudaGetSymbolAddress((void**)&wol, g_wol);

    cudaFuncSetAttribute(gemm_mma, cudaFuncAttributeMaxDynamicSharedMemorySize, GEMM_DYN);

    rope_table_kernel<<<(TT*32 + 255) / 256, 256>>>();
    split_kernel<<<(MTOT*CC/4 + 255) / 256, 256>>>((const float4*)x,    (__nv_bfloat162*)xh,  (__nv_bfloat162*)xl,  MTOT*CC/4);
    split_kernel<<<(QKVC*CC/4 + 255) / 256, 256>>>((const float4*)Wqkv, (__nv_bfloat162*)wqh, (__nv_bfloat162*)wql, QKVC*CC/4);
    split_kernel<<<(CC*CC/4   + 255) / 256, 256>>>((const float4*)Wout, (__nv_bfloat162*)woh, (__nv_bfloat162*)wol, CC*CC/4);

    // GEMM1: qkv = x @ Wqkv^T  (M=16384, N=3072, K=1024)
    {
        dim3 grid(QKVC / BN, MTOT / BM);
        gemm_mma<<<grid, 256, GEMM_DYN>>>(xh, xl, wqh, wql, qkv_p, QKVC, CC);
    }

    // fused RoPE + head-attention + scramble + bf16 split
    attn_kernel<<<MTOT, 256>>>();

    // GEMM2: out = scr @ Wout^T (M=16384, N=1024, K=1024)
    {
        dim3 grid(CC / BN, MTOT / BM);
        gemm_mma<<<grid, 256, GEMM_DYN>>>(sh, sl, woh, wol, out, CC, CC);
    }
}

// round 6
// speedup vs baseline: 2.8508x; 1.3533x over previous
#include <cuda_runtime.h>
#include <cuda_fp16.h>
#include <math.h>
#include <stdint.h>

#define BB 2
#define TT 8192
#define CC 1024
#define HH 16
#define DD 64
#define MTOT (BB*TT)        // 16384
#define QKVC (3*CC)         // 3072

// ---------------- device scratch ----------------
__device__ float g_qkv[(size_t)MTOT * QKVC];       // 192 MB fp32
__device__ __half g_xh[(size_t)MTOT * CC];         // x hi/lo (fp16 2-term split)
__device__ __half g_xl[(size_t)MTOT * CC];
__device__ __half g_sh[(size_t)MTOT * CC];         // scrambled attn out hi/lo
__device__ __half g_sl[(size_t)MTOT * CC];
__device__ __half g_wqh[(size_t)QKVC * CC];        // weights: hi only
__device__ __half g_woh[(size_t)CC * CC];
__device__ float g_cos[TT * 32];
__device__ float g_sin[TT * 32];

// ---------------- PTX helpers (compute_103 baseline) ----------------
__device__ __forceinline__ uint32_t smem_u32(const void* p) {
    uint32_t a;
    asm("{ .reg .u64 t; cvta.to.shared.u64 t, %1; cvt.u32.u64 %0, t; }" : "=r"(a) : "l"(p));
    return a;
}
__device__ __forceinline__ void cp16(uint32_t s, const void* g) {
    asm volatile("cp.async.cg.shared.global [%0], [%1], 16;" :: "r"(s), "l"(g));
}
#define CP_COMMIT() asm volatile("cp.async.commit_group;" ::: "memory")
#define CP_WAIT(n)  asm volatile("cp.async.wait_group %0;" :: "n"(n) : "memory")

__device__ __forceinline__ void ldsm_x4(uint32_t* r, uint32_t addr) {
    asm volatile("ldmatrix.sync.aligned.m8n8.x4.shared.b16 {%0,%1,%2,%3}, [%4];"
                 : "=r"(r[0]), "=r"(r[1]), "=r"(r[2]), "=r"(r[3]) : "r"(addr));
}
#define MMA_F16(d, a, b0, b1) \
    asm volatile("mma.sync.aligned.m16n8k16.row.col.f32.f16.f16.f32 " \
                 "{%0,%1,%2,%3}, {%4,%5,%6,%7}, {%8,%9}, {%0,%1,%2,%3};" \
                 : "+f"((d)[0]), "+f"((d)[1]), "+f"((d)[2]), "+f"((d)[3]) \
                 : "r"((a)[0]), "r"((a)[1]), "r"((a)[2]), "r"((a)[3]), \
                   "r"(b0), "r"(b1))

// ---------------- small kernels ----------------
__global__ void rope_table_kernel() {
    int idx = blockIdx.x * blockDim.x + threadIdx.x;
    if (idx >= TT * 32) return;
    int t = idx >> 5, d2 = idx & 31;
    float invf = (float)pow(10000.0, -(double)d2 / 32.0);
    float ang = __fmul_rn((float)t, invf);
    g_cos[idx] = (float)cos((double)ang);
    g_sin[idx] = (float)sin((double)ang);
}

// fp32 -> fp16 hi + fp16 lo (residual)
__global__ void split2_kernel(const float4* __restrict__ in,
                              __half2* __restrict__ hi,
                              __half2* __restrict__ lo, int n4) {
    int i = blockIdx.x * blockDim.x + threadIdx.x;
    if (i >= n4) return;
    float4 v = in[i];
    __half h0 = __float2half_rn(v.x), h1 = __float2half_rn(v.y);
    __half h2 = __float2half_rn(v.z), h3 = __float2half_rn(v.w);
    __half2 H0; H0.x = h0; H0.y = h1;
    __half2 H1; H1.x = h2; H1.y = h3;
    __half2 L0; L0.x = __float2half_rn(v.x - __half2float(h0));
                L0.y = __float2half_rn(v.y - __half2float(h1));
    __half2 L1; L1.x = __float2half_rn(v.z - __half2float(h2));
                L1.y = __float2half_rn(v.w - __half2float(h3));
    hi[2*i] = H0; hi[2*i+1] = H1;
    lo[2*i] = L0; lo[2*i+1] = L1;
}

// fp32 -> fp16 hi only (for weights)
__global__ void split1_kernel(const float4* __restrict__ in,
                              __half2* __restrict__ hi, int n4) {
    int i = blockIdx.x * blockDim.x + threadIdx.x;
    if (i >= n4) return;
    float4 v = in[i];
    __half2 H0; H0.x = __float2half_rn(v.x); H0.y = __float2half_rn(v.y);
    __half2 H1; H1.x = __float2half_rn(v.z); H1.y = __float2half_rn(v.w);
    hi[2*i] = H0; hi[2*i+1] = H1;
}

// ---------------- mma.sync GEMM (NT): C[m,n] = sum_k A[m,k]*B[n,k] ----------------
// fp16x2 split: (Ah + Al)*Bh, fp32 accum. Error ~ A*(B-Bh) ~ 1.5e-4 rel.
// 128x128 tile, BK=64, 4-stage cp.async pipeline, SW128 swizzle.
#define BM 128
#define BN 128
#define BKQ 64
#define T_AH 0
#define T_AL (16*1024)
#define T_BH (32*1024)
#define STG  (48*1024)
#define NSTAGE 4
#define GEMM_DYN (NSTAGE*STG + 1024)

extern __shared__ char dynsmem[];

__global__ __launch_bounds__(256, 1) void gemm_mma(
    const __half* __restrict__ Ah, const __half* __restrict__ Al,
    const __half* __restrict__ Bh,
    float* __restrict__ C, int ldc, int K)
{
    const int tid  = threadIdx.x;
    const int wid  = tid >> 5;
    const int lane = tid & 31;
    const int m0 = blockIdx.y * BM;
    const int n0 = blockIdx.x * BN;
    const int wm = (wid >> 1) * 32;   // warp m offset in tile
    const int wn = (wid & 1) * 64;    // warp n offset in tile

    uint32_t sbase = (smem_u32(dynsmem) + 1023u) & ~1023u;

    // ---- loader setup: thread -> row tid/2, 4 x 16B chunks per tensor ----
    const int lrow = tid >> 1;
    const int lc4  = (tid & 1) * 4;
    uint32_t soff[4];
#pragma unroll
    for (int c = 0; c < 4; ++c) {
        uint32_t off = (uint32_t)lrow * 128 + (uint32_t)(lc4 + c) * 16;
        soff[c] = off ^ ((off >> 3) & 0x70);
    }
    const __half* gAh = Ah + (size_t)(m0 + lrow) * K + lc4 * 8;
    const __half* gAl = Al + (size_t)(m0 + lrow) * K + lc4 * 8;
    const __half* gBh = Bh + (size_t)(n0 + lrow) * K + lc4 * 8;

    auto load_stage = [&](int stage, int iter) {
        uint32_t st = sbase + (uint32_t)stage * STG;
        const int k0 = iter * BKQ;
#pragma unroll
        for (int c = 0; c < 4; ++c) {
            cp16(st + T_AH + soff[c], gAh + k0 + c * 8);
            cp16(st + T_AL + soff[c], gAl + k0 + c * 8);
            cp16(st + T_BH + soff[c], gBh + k0 + c * 8);
        }
        CP_COMMIT();
    };

    // ---- ldmatrix address precompute ----
    uint32_t a_rt[2], a_xr[2];
#pragma unroll
    for (int ti = 0; ti < 2; ++ti) {
        int r = wm + ti * 16 + (lane & 15);
        a_rt[ti] = (uint32_t)r * 128;
        a_xr[ti] = (uint32_t)(r & 7) << 4;
    }
    const uint32_t a_cb = (uint32_t)(lane >> 4) * 16;
    uint32_t b_rt[4], b_xr[4];
#pragma unroll
    for (int ni = 0; ni < 4; ++ni) {
        int r = wn + ni * 16 + (lane & 7) + (lane >> 4) * 8;
        b_rt[ni] = (uint32_t)r * 128;
        b_xr[ni] = (uint32_t)(r & 7) << 4;
    }
    const uint32_t b_cb = (uint32_t)((lane >> 3) & 1) * 16;

    float acc[2][8][4];
#pragma unroll
    for (int i = 0; i < 2; ++i)
#pragma unroll
        for (int j = 0; j < 8; ++j)
#pragma unroll
            for (int q = 0; q < 4; ++q) acc[i][j][q] = 0.f;

    const int niter = K / BKQ;   // 16

#pragma unroll
    for (int s = 0; s < NSTAGE - 1; ++s) load_stage(s, s);

    for (int i = 0; i < niter; ++i) {
        if (i + NSTAGE - 1 < niter) { CP_WAIT(NSTAGE - 2); } else { CP_WAIT(0); }
        __syncthreads();
        if (i + NSTAGE - 1 < niter) load_stage((i + NSTAGE - 1) % NSTAGE, i + NSTAGE - 1);

        uint32_t base = sbase + (uint32_t)(i % NSTAGE) * STG;
#pragma unroll
        for (int ks = 0; ks < 4; ++ks) {
            const uint32_t kb = (uint32_t)ks * 32;
            uint32_t ah[2][4], al[2][4], bh[4][4];
#pragma unroll
            for (int ni = 0; ni < 4; ++ni)
                ldsm_x4(bh[ni], base + T_BH + b_rt[ni] + ((b_cb + kb) ^ b_xr[ni]));
#pragma unroll
            for (int ti = 0; ti < 2; ++ti)
                ldsm_x4(ah[ti], base + T_AH + a_rt[ti] + ((a_cb + kb) ^ a_xr[ti]));
#pragma unroll
            for (int ti = 0; ti < 2; ++ti)
                ldsm_x4(al[ti], base + T_AL + a_rt[ti] + ((a_cb + kb) ^ a_xr[ti]));

            // term-major: hi term then lo term, 16 accumulators apart
#pragma unroll
            for (int mi = 0; mi < 2; ++mi)
#pragma unroll
                for (int ni = 0; ni < 4; ++ni) {
                    MMA_F16(acc[mi][2*ni],   ah[mi], bh[ni][0], bh[ni][1]);
                    MMA_F16(acc[mi][2*ni+1], ah[mi], bh[ni][2], bh[ni][3]);
                }
#pragma unroll
            for (int mi = 0; mi < 2; ++mi)
#pragma unroll
                for (int ni = 0; ni < 4; ++ni) {
                    MMA_F16(acc[mi][2*ni],   al[mi], bh[ni][0], bh[ni][1]);
                    MMA_F16(acc[mi][2*ni+1], al[mi], bh[ni][2], bh[ni][3]);
                }
        }
        __syncthreads();
    }

    // ---- epilogue ----
#pragma unroll
    for (int mi = 0; mi < 2; ++mi) {
        int gm = m0 + wm + mi * 16 + (lane >> 2);
#pragma unroll
        for (int ni = 0; ni < 8; ++ni) {
            int gn = n0 + wn + ni * 8 + (lane & 3) * 2;
            float2 v0 = make_float2(acc[mi][ni][0], acc[mi][ni][1]);
            float2 v1 = make_float2(acc[mi][ni][2], acc[mi][ni][3]);
            *(float2*)(C + (size_t)gm * ldc + gn) = v0;
            *(float2*)(C + (size_t)(gm + 8) * ldc + gn) = v1;
        }
    }
}

// ---------------- fused RoPE + per-token 16x16 head-attn + scrambled fp16 split ----------------
#define PAD 65
__global__ __launch_bounds__(256) void attn_kernel()
{
    __shared__ float q [HH][PAD];
    __shared__ float kk[HH][PAD];
    __shared__ float vv[HH][PAD];
    __shared__ float sc[HH][17];
    __shared__ float cs[32], sn[32];

    const int tok = blockIdx.x;
    const int b = tok >> 13;
    const int t = tok & (TT - 1);
    const int tid = threadIdx.x;

    if (tid < 32) { cs[tid] = g_cos[t*32 + tid]; sn[tid] = g_sin[t*32 + tid]; }

    const float* row = g_qkv + (size_t)tok * QKVC;
#pragma unroll
    for (int r = 0; r < 12; ++r) {
        int idx = tid + 256 * r;
        float val = row[idx];
        int s = idx >> 10;
        int h = (idx >> 6) & 15;
        int d = idx & 63;
        if      (s == 0) q [h][d] = val;
        else if (s == 1) kk[h][d] = val;
        else             vv[h][d] = val;
    }
    __syncthreads();

#pragma unroll
    for (int r = 0; r < 4; ++r) {
        int idx = tid + 256 * r;
        int which = idx >> 9;
        int h = (idx >> 5) & 15;
        int d2 = idx & 31;
        float c = cs[d2], s = sn[d2];
        float* buf = which ? &kk[0][0] : &q[0][0];
        float x1 = buf[h*PAD + 2*d2];
        float x2 = buf[h*PAD + 2*d2 + 1];
        buf[h*PAD + 2*d2]     = x1*c - x2*s;
        buf[h*PAD + 2*d2 + 1] = x2*c + x1*s;
    }
    __syncthreads();

    {
        int hq = tid >> 4, hk = tid & 15;
        float s = 0.f;
#pragma unroll
        for (int d = 0; d < DD; ++d) s = fmaf(q[hq][d], kk[hk][d], s);
        sc[hq][hk] = s * 0.125f;
    }
    __syncthreads();

    if (tid < 16) {
        float mx = -1e30f;
#pragma unroll
        for (int j = 0; j < 16; ++j) mx = fmaxf(mx, sc[tid][j]);
        float sum = 0.f;
#pragma unroll
        for (int j = 0; j < 16; ++j) { float e = expf(sc[tid][j] - mx); sc[tid][j] = e; sum += e; }
        float inv = 1.f / sum;
#pragma unroll
        for (int j = 0; j < 16; ++j) sc[tid][j] *= inv;
    }
    __syncthreads();

    const size_t obase = ((size_t)b * TT + (t >> 4)) * (size_t)CC + (size_t)(t & 15) * DD;
#pragma unroll
    for (int r = 0; r < 4; ++r) {
        int idx = tid + 256 * r;
        int hq = idx >> 6, d = idx & 63;
        float o = 0.f;
#pragma unroll
        for (int hk = 0; hk < 16; ++hk) o = fmaf(sc[hq][hk], vv[hk][d], o);
        size_t oi = obase + (size_t)hq * 512 * CC + d;
        __half h = __float2half_rn(o);
        g_sh[oi] = h;
        g_sl[oi] = __float2half_rn(o - __half2float(h));
    }
}

// ---------------------------------------------------------------------------
extern "C" void kernel_launch(void* const* d_in, const int* in_sizes, int n_in,
                              void* d_out, int out_size)
{
    const float* x    = (const float*)d_in[0];
    const float* Wqkv = (const float*)d_in[1];
    const float* Wout = (const float*)d_in[2];
    float* out = (float*)d_out;

    float *qkv_p;
    __half *xh, *xl, *sh, *sl, *wqh, *woh;
    cudaGetSymbolAddress((void**)&qkv_p, g_qkv);
    cudaGetSymbolAddress((void**)&xh, g_xh);   cudaGetSymbolAddress((void**)&xl, g_xl);
    cudaGetSymbolAddress((void**)&sh, g_sh);   cudaGetSymbolAddress((void**)&sl, g_sl);
    cudaGetSymbolAddress((void**)&wqh, g_wqh); cudaGetSymbolAddress((void**)&woh, g_woh);

    cudaFuncSetAttribute(gemm_mma, cudaFuncAttributeMaxDynamicSharedMemorySize, GEMM_DYN);

    rope_table_kernel<<<(TT*32 + 255) / 256, 256>>>();
    split2_kernel<<<(MTOT*CC/4 + 255) / 256, 256>>>((const float4*)x,    (__half2*)xh, (__half2*)xl, MTOT*CC/4);
    split1_kernel<<<(QKVC*CC/4 + 255) / 256, 256>>>((const float4*)Wqkv, (__half2*)wqh, QKVC*CC/4);
    split1_kernel<<<(CC*CC/4   + 255) / 256, 256>>>((const float4*)Wout, (__half2*)woh, CC*CC/4);

    // GEMM1: qkv = x @ Wqkv^T  (M=16384, N=3072, K=1024)
    {
        dim3 grid(QKVC / BN, MTOT / BM);
        gemm_mma<<<grid, 256, GEMM_DYN>>>(xh, xl, wqh, qkv_p, QKVC, CC);
    }

    // fused RoPE + head-attention + scramble + fp16 split
    attn_kernel<<<MTOT, 256>>>();

    // GEMM2: out = scr @ Wout^T (M=16384, N=1024, K=1024)
    {
        dim3 grid(CC / BN, MTOT / BM);
        gemm_mma<<<grid, 256, GEMM_DYN>>>(sh, sl, woh, out, CC, CC);
    }
}

// round 7
// speedup vs baseline: 4.0124x; 1.4075x over previous
#include <cuda_runtime.h>
#include <cuda_fp16.h>
#include <math.h>
#include <stdint.h>

#define BB 2
#define TT 8192
#define CC 1024
#define HH 16
#define DD 64
#define MTOT (BB*TT)        // 16384
#define QKVC (3*CC)         // 3072

// ---------------- device scratch ----------------
__device__ float g_qkv[(size_t)MTOT * QKVC];       // 192 MB fp32
__device__ __half g_xh[(size_t)MTOT * CC];         // x (fp16)
__device__ __half g_sh[(size_t)MTOT * CC];         // scrambled attn out (fp16)
__device__ __half g_wqh[(size_t)QKVC * CC];        // Wqkv (fp16)
__device__ __half g_woh[(size_t)CC * CC];          // Wout (fp16)
__device__ float g_cos[TT * 32];
__device__ float g_sin[TT * 32];

// ---------------- PTX helpers (compute_103 baseline) ----------------
__device__ __forceinline__ uint32_t smem_u32(const void* p) {
    uint32_t a;
    asm("{ .reg .u64 t; cvta.to.shared.u64 t, %1; cvt.u32.u64 %0, t; }" : "=r"(a) : "l"(p));
    return a;
}
__device__ __forceinline__ void cp16(uint32_t s, const void* g) {
    asm volatile("cp.async.cg.shared.global [%0], [%1], 16;" :: "r"(s), "l"(g));
}
#define CP_COMMIT() asm volatile("cp.async.commit_group;" ::: "memory")
#define CP_WAIT(n)  asm volatile("cp.async.wait_group %0;" :: "n"(n) : "memory")

__device__ __forceinline__ void ldsm_x4(uint32_t* r, uint32_t addr) {
    asm volatile("ldmatrix.sync.aligned.m8n8.x4.shared.b16 {%0,%1,%2,%3}, [%4];"
                 : "=r"(r[0]), "=r"(r[1]), "=r"(r[2]), "=r"(r[3]) : "r"(addr));
}
#define MMA_F16(d, a, b0, b1) \
    asm volatile("mma.sync.aligned.m16n8k16.row.col.f32.f16.f16.f32 " \
                 "{%0,%1,%2,%3}, {%4,%5,%6,%7}, {%8,%9}, {%0,%1,%2,%3};" \
                 : "+f"((d)[0]), "+f"((d)[1]), "+f"((d)[2]), "+f"((d)[3]) \
                 : "r"((a)[0]), "r"((a)[1]), "r"((a)[2]), "r"((a)[3]), \
                   "r"(b0), "r"(b1))

// ---------------- small kernels ----------------
__global__ void rope_table_kernel() {
    int idx = blockIdx.x * blockDim.x + threadIdx.x;
    if (idx >= TT * 32) return;
    int t = idx >> 5, d2 = idx & 31;
    float invf = (float)pow(10000.0, -(double)d2 / 32.0);
    float ang = __fmul_rn((float)t, invf);
    g_cos[idx] = (float)cos((double)ang);
    g_sin[idx] = (float)sin((double)ang);
}

// fp32 -> fp16
__global__ void cvt_kernel(const float4* __restrict__ in,
                           __half2* __restrict__ hi, int n4) {
    int i = blockIdx.x * blockDim.x + threadIdx.x;
    if (i >= n4) return;
    float4 v = in[i];
    __half2 H0; H0.x = __float2half_rn(v.x); H0.y = __float2half_rn(v.y);
    __half2 H1; H1.x = __float2half_rn(v.z); H1.y = __float2half_rn(v.w);
    hi[2*i] = H0; hi[2*i+1] = H1;
}

// ---------------- mma.sync GEMM (NT): C[m,n] = sum_k A[m,k]*B[n,k] ----------------
// pure fp16, fp32 accum. 128x128 tile, BK=64, 5-stage cp.async, SW128 swizzle.
#define BM 128
#define BN 128
#define BKQ 64
#define T_AH 0
#define T_BH (16*1024)
#define STG  (32*1024)
#define NSTAGE 5
#define GEMM_DYN (NSTAGE*STG + 1024)

extern __shared__ char dynsmem[];

__global__ __launch_bounds__(256, 1) void gemm_mma(
    const __half* __restrict__ Ah,
    const __half* __restrict__ Bh,
    float* __restrict__ C, int ldc, int K)
{
    const int tid  = threadIdx.x;
    const int wid  = tid >> 5;
    const int lane = tid & 31;
    const int m0 = blockIdx.y * BM;
    const int n0 = blockIdx.x * BN;
    const int wm = (wid >> 1) * 32;   // warp m offset in tile
    const int wn = (wid & 1) * 64;    // warp n offset in tile

    uint32_t sbase = (smem_u32(dynsmem) + 1023u) & ~1023u;

    // ---- loader setup: thread -> row tid/2, 4 x 16B chunks per tensor ----
    const int lrow = tid >> 1;
    const int lc4  = (tid & 1) * 4;
    uint32_t soff[4];
#pragma unroll
    for (int c = 0; c < 4; ++c) {
        uint32_t off = (uint32_t)lrow * 128 + (uint32_t)(lc4 + c) * 16;
        soff[c] = off ^ ((off >> 3) & 0x70);
    }
    const __half* gAh = Ah + (size_t)(m0 + lrow) * K + lc4 * 8;
    const __half* gBh = Bh + (size_t)(n0 + lrow) * K + lc4 * 8;

    auto load_stage = [&](int stage, int iter) {
        uint32_t st = sbase + (uint32_t)stage * STG;
        const int k0 = iter * BKQ;
#pragma unroll
        for (int c = 0; c < 4; ++c) {
            cp16(st + T_AH + soff[c], gAh + k0 + c * 8);
            cp16(st + T_BH + soff[c], gBh + k0 + c * 8);
        }
        CP_COMMIT();
    };

    // ---- ldmatrix address precompute ----
    uint32_t a_rt[2], a_xr[2];
#pragma unroll
    for (int ti = 0; ti < 2; ++ti) {
        int r = wm + ti * 16 + (lane & 15);
        a_rt[ti] = (uint32_t)r * 128;
        a_xr[ti] = (uint32_t)(r & 7) << 4;
    }
    const uint32_t a_cb = (uint32_t)(lane >> 4) * 16;
    uint32_t b_rt[4], b_xr[4];
#pragma unroll
    for (int ni = 0; ni < 4; ++ni) {
        int r = wn + ni * 16 + (lane & 7) + (lane >> 4) * 8;
        b_rt[ni] = (uint32_t)r * 128;
        b_xr[ni] = (uint32_t)(r & 7) << 4;
    }
    const uint32_t b_cb = (uint32_t)((lane >> 3) & 1) * 16;

    float acc[2][8][4];
#pragma unroll
    for (int i = 0; i < 2; ++i)
#pragma unroll
        for (int j = 0; j < 8; ++j)
#pragma unroll
            for (int q = 0; q < 4; ++q) acc[i][j][q] = 0.f;

    const int niter = K / BKQ;   // 16

#pragma unroll
    for (int s = 0; s < NSTAGE - 1; ++s) load_stage(s, s);

    for (int i = 0; i < niter; ++i) {
        if (i + NSTAGE - 1 < niter) { CP_WAIT(NSTAGE - 2); } else { CP_WAIT(0); }
        __syncthreads();
        if (i + NSTAGE - 1 < niter) load_stage((i + NSTAGE - 1) % NSTAGE, i + NSTAGE - 1);

        uint32_t base = sbase + (uint32_t)(i % NSTAGE) * STG;
#pragma unroll
        for (int ks = 0; ks < 4; ++ks) {
            const uint32_t kb = (uint32_t)ks * 32;
            uint32_t ah[2][4], bh[4][4];
#pragma unroll
            for (int ni = 0; ni < 4; ++ni)
                ldsm_x4(bh[ni], base + T_BH + b_rt[ni] + ((b_cb + kb) ^ b_xr[ni]));
#pragma unroll
            for (int ti = 0; ti < 2; ++ti)
                ldsm_x4(ah[ti], base + T_AH + a_rt[ti] + ((a_cb + kb) ^ a_xr[ti]));

#pragma unroll
            for (int mi = 0; mi < 2; ++mi)
#pragma unroll
                for (int ni = 0; ni < 4; ++ni) {
                    MMA_F16(acc[mi][2*ni],   ah[mi], bh[ni][0], bh[ni][1]);
                    MMA_F16(acc[mi][2*ni+1], ah[mi], bh[ni][2], bh[ni][3]);
                }
        }
        __syncthreads();
    }

    // ---- epilogue ----
#pragma unroll
    for (int mi = 0; mi < 2; ++mi) {
        int gm = m0 + wm + mi * 16 + (lane >> 2);
#pragma unroll
        for (int ni = 0; ni < 8; ++ni) {
            int gn = n0 + wn + ni * 8 + (lane & 3) * 2;
            float2 v0 = make_float2(acc[mi][ni][0], acc[mi][ni][1]);
            float2 v1 = make_float2(acc[mi][ni][2], acc[mi][ni][3]);
            *(float2*)(C + (size_t)gm * ldc + gn) = v0;
            *(float2*)(C + (size_t)(gm + 8) * ldc + gn) = v1;
        }
    }
}

// ---------------- fused RoPE + per-token 16x16 head-attn + scrambled fp16 store ----------------
#define PAD 65
__global__ __launch_bounds__(256) void attn_kernel()
{
    __shared__ float q [HH][PAD];
    __shared__ float kk[HH][PAD];
    __shared__ float vv[HH][PAD];
    __shared__ float sc[HH][17];
    __shared__ float cs[32], sn[32];

    const int tok = blockIdx.x;
    const int b = tok >> 13;
    const int t = tok & (TT - 1);
    const int tid = threadIdx.x;

    if (tid < 32) { cs[tid] = g_cos[t*32 + tid]; sn[tid] = g_sin[t*32 + tid]; }

    const float* row = g_qkv + (size_t)tok * QKVC;
#pragma unroll
    for (int r = 0; r < 12; ++r) {
        int idx = tid + 256 * r;
        float val = row[idx];
        int s = idx >> 10;
        int h = (idx >> 6) & 15;
        int d = idx & 63;
        if      (s == 0) q [h][d] = val;
        else if (s == 1) kk[h][d] = val;
        else             vv[h][d] = val;
    }
    __syncthreads();

#pragma unroll
    for (int r = 0; r < 4; ++r) {
        int idx = tid + 256 * r;
        int which = idx >> 9;
        int h = (idx >> 5) & 15;
        int d2 = idx & 31;
        float c = cs[d2], s = sn[d2];
        float* buf = which ? &kk[0][0] : &q[0][0];
        float x1 = buf[h*PAD + 2*d2];
        float x2 = buf[h*PAD + 2*d2 + 1];
        buf[h*PAD + 2*d2]     = x1*c - x2*s;
        buf[h*PAD + 2*d2 + 1] = x2*c + x1*s;
    }
    __syncthreads();

    {
        int hq = tid >> 4, hk = tid & 15;
        float s = 0.f;
#pragma unroll
        for (int d = 0; d < DD; ++d) s = fmaf(q[hq][d], kk[hk][d], s);
        sc[hq][hk] = s * 0.125f;
    }
    __syncthreads();

    if (tid < 16) {
        float mx = -1e30f;
#pragma unroll
        for (int j = 0; j < 16; ++j) mx = fmaxf(mx, sc[tid][j]);
        float sum = 0.f;
#pragma unroll
        for (int j = 0; j < 16; ++j) { float e = expf(sc[tid][j] - mx); sc[tid][j] = e; sum += e; }
        float inv = 1.f / sum;
#pragma unroll
        for (int j = 0; j < 16; ++j) sc[tid][j] *= inv;
    }
    __syncthreads();

    const size_t obase = ((size_t)b * TT + (t >> 4)) * (size_t)CC + (size_t)(t & 15) * DD;
#pragma unroll
    for (int r = 0; r < 4; ++r) {
        int idx = tid + 256 * r;
        int hq = idx >> 6, d = idx & 63;
        float o = 0.f;
#pragma unroll
        for (int hk = 0; hk < 16; ++hk) o = fmaf(sc[hq][hk], vv[hk][d], o);
        g_sh[obase + (size_t)hq * 512 * CC + d] = __float2half_rn(o);
    }
}

// ---------------------------------------------------------------------------
extern "C" void kernel_launch(void* const* d_in, const int* in_sizes, int n_in,
                              void* d_out, int out_size)
{
    const float* x    = (const float*)d_in[0];
    const float* Wqkv = (const float*)d_in[1];
    const float* Wout = (const float*)d_in[2];
    float* out = (float*)d_out;

    float *qkv_p;
    __half *xh, *sh, *wqh, *woh;
    cudaGetSymbolAddress((void**)&qkv_p, g_qkv);
    cudaGetSymbolAddress((void**)&xh, g_xh);
    cudaGetSymbolAddress((void**)&sh, g_sh);
    cudaGetSymbolAddress((void**)&wqh, g_wqh);
    cudaGetSymbolAddress((void**)&woh, g_woh);

    cudaFuncSetAttribute(gemm_mma, cudaFuncAttributeMaxDynamicSharedMemorySize, GEMM_DYN);

    rope_table_kernel<<<(TT*32 + 255) / 256, 256>>>();
    cvt_kernel<<<(MTOT*CC/4 + 255) / 256, 256>>>((const float4*)x,    (__half2*)xh,  MTOT*CC/4);
    cvt_kernel<<<(QKVC*CC/4 + 255) / 256, 256>>>((const float4*)Wqkv, (__half2*)wqh, QKVC*CC/4);
    cvt_kernel<<<(CC*CC/4   + 255) / 256, 256>>>((const float4*)Wout, (__half2*)woh, CC*CC/4);

    // GEMM1: qkv = x @ Wqkv^T  (M=16384, N=3072, K=1024)
    {
        dim3 grid(QKVC / BN, MTOT / BM);
        gemm_mma<<<grid, 256, GEMM_DYN>>>(xh, wqh, qkv_p, QKVC, CC);
    }

    // fused RoPE + head-attention + scramble
    attn_kernel<<<MTOT, 256>>>();

    // GEMM2: out = scr @ Wout^T (M=16384, N=1024, K=1024)
    {
        dim3 grid(CC / BN, MTOT / BM);
        gemm_mma<<<grid, 256, GEMM_DYN>>>(sh, woh, out, CC, CC);
    }
}

// round 8
// speedup vs baseline: 4.0552x; 1.0107x over previous
#include <cuda_runtime.h>
#include <cuda_fp16.h>
#include <math.h>
#include <stdint.h>

#define BB 2
#define TT 8192
#define CC 1024
#define HH 16
#define DD 64
#define MTOT (BB*TT)        // 16384
#define QKVC (3*CC)         // 3072

// ---------------- device scratch ----------------
__device__ __half g_qkv[(size_t)MTOT * QKVC];      // 96 MB fp16
__device__ __half g_xh[(size_t)MTOT * CC];         // x (fp16)
__device__ __half g_sh[(size_t)MTOT * CC];         // scrambled attn out (fp16)
__device__ __half g_wqh[(size_t)QKVC * CC];        // Wqkv (fp16)
__device__ __half g_woh[(size_t)CC * CC];          // Wout (fp16)
__device__ float g_cos[TT * 32];
__device__ float g_sin[TT * 32];

// ---------------- PTX helpers (compute_103 baseline) ----------------
__device__ __forceinline__ uint32_t smem_u32(const void* p) {
    uint32_t a;
    asm("{ .reg .u64 t; cvta.to.shared.u64 t, %1; cvt.u32.u64 %0, t; }" : "=r"(a) : "l"(p));
    return a;
}
__device__ __forceinline__ void cp16(uint32_t s, const void* g) {
    asm volatile("cp.async.cg.shared.global [%0], [%1], 16;" :: "r"(s), "l"(g));
}
#define CP_COMMIT() asm volatile("cp.async.commit_group;" ::: "memory")
#define CP_WAIT(n)  asm volatile("cp.async.wait_group %0;" :: "n"(n) : "memory")

__device__ __forceinline__ void ldsm_x4(uint32_t* r, uint32_t addr) {
    asm volatile("ldmatrix.sync.aligned.m8n8.x4.shared.b16 {%0,%1,%2,%3}, [%4];"
                 : "=r"(r[0]), "=r"(r[1]), "=r"(r[2]), "=r"(r[3]) : "r"(addr));
}
#define MMA_F16(d, a, b0, b1) \
    asm volatile("mma.sync.aligned.m16n8k16.row.col.f32.f16.f16.f32 " \
                 "{%0,%1,%2,%3}, {%4,%5,%6,%7}, {%8,%9}, {%0,%1,%2,%3};" \
                 : "+f"((d)[0]), "+f"((d)[1]), "+f"((d)[2]), "+f"((d)[3]) \
                 : "r"((a)[0]), "r"((a)[1]), "r"((a)[2]), "r"((a)[3]), \
                   "r"(b0), "r"(b1))

// ---------------- small kernels ----------------
__global__ void rope_table_kernel() {
    int idx = blockIdx.x * blockDim.x + threadIdx.x;
    if (idx >= TT * 32) return;
    int t = idx >> 5, d2 = idx & 31;
    float invf = (float)pow(10000.0, -(double)d2 / 32.0);
    float ang = __fmul_rn((float)t, invf);
    g_cos[idx] = (float)cos((double)ang);
    g_sin[idx] = (float)sin((double)ang);
}

// fp32 -> fp16
__global__ void cvt_kernel(const float4* __restrict__ in,
                           __half2* __restrict__ hi, int n4) {
    int i = blockIdx.x * blockDim.x + threadIdx.x;
    if (i >= n4) return;
    float4 v = in[i];
    __half2 H0; H0.x = __float2half_rn(v.x); H0.y = __float2half_rn(v.y);
    __half2 H1; H1.x = __float2half_rn(v.z); H1.y = __float2half_rn(v.w);
    hi[2*i] = H0; hi[2*i+1] = H1;
}

// ---------------- mma.sync GEMM (NT): C[m,n] = sum_k A[m,k]*B[n,k] ----------------
// pure fp16, fp32 accum. 128x128 tile, BK=64, 5-stage cp.async, SW128 swizzle.
// Output type templated: float (GEMM2) or __half (GEMM1 -> qkv).
#define BM 128
#define BN 128
#define BKQ 64
#define T_AH 0
#define T_BH (16*1024)
#define STG  (32*1024)
#define NSTAGE 5
#define GEMM_DYN (NSTAGE*STG + 1024)

extern __shared__ char dynsmem[];

template <typename OutT>
__global__ __launch_bounds__(256, 1) void gemm_mma(
    const __half* __restrict__ Ah,
    const __half* __restrict__ Bh,
    OutT* __restrict__ C, int ldc, int K)
{
    const int tid  = threadIdx.x;
    const int wid  = tid >> 5;
    const int lane = tid & 31;
    const int m0 = blockIdx.y * BM;
    const int n0 = blockIdx.x * BN;
    const int wm = (wid >> 1) * 32;
    const int wn = (wid & 1) * 64;

    uint32_t sbase = (smem_u32(dynsmem) + 1023u) & ~1023u;

    const int lrow = tid >> 1;
    const int lc4  = (tid & 1) * 4;
    uint32_t soff[4];
#pragma unroll
    for (int c = 0; c < 4; ++c) {
        uint32_t off = (uint32_t)lrow * 128 + (uint32_t)(lc4 + c) * 16;
        soff[c] = off ^ ((off >> 3) & 0x70);
    }
    const __half* gAh = Ah + (size_t)(m0 + lrow) * K + lc4 * 8;
    const __half* gBh = Bh + (size_t)(n0 + lrow) * K + lc4 * 8;

    auto load_stage = [&](int stage, int iter) {
        uint32_t st = sbase + (uint32_t)stage * STG;
        const int k0 = iter * BKQ;
#pragma unroll
        for (int c = 0; c < 4; ++c) {
            cp16(st + T_AH + soff[c], gAh + k0 + c * 8);
            cp16(st + T_BH + soff[c], gBh + k0 + c * 8);
        }
        CP_COMMIT();
    };

    uint32_t a_rt[2], a_xr[2];
#pragma unroll
    for (int ti = 0; ti < 2; ++ti) {
        int r = wm + ti * 16 + (lane & 15);
        a_rt[ti] = (uint32_t)r * 128;
        a_xr[ti] = (uint32_t)(r & 7) << 4;
    }
    const uint32_t a_cb = (uint32_t)(lane >> 4) * 16;
    uint32_t b_rt[4], b_xr[4];
#pragma unroll
    for (int ni = 0; ni < 4; ++ni) {
        int r = wn + ni * 16 + (lane & 7) + (lane >> 4) * 8;
        b_rt[ni] = (uint32_t)r * 128;
        b_xr[ni] = (uint32_t)(r & 7) << 4;
    }
    const uint32_t b_cb = (uint32_t)((lane >> 3) & 1) * 16;

    float acc[2][8][4];
#pragma unroll
    for (int i = 0; i < 2; ++i)
#pragma unroll
        for (int j = 0; j < 8; ++j)
#pragma unroll
            for (int q = 0; q < 4; ++q) acc[i][j][q] = 0.f;

    const int niter = K / BKQ;   // 16

#pragma unroll
    for (int s = 0; s < NSTAGE - 1; ++s) load_stage(s, s);

    for (int i = 0; i < niter; ++i) {
        if (i + NSTAGE - 1 < niter) { CP_WAIT(NSTAGE - 2); } else { CP_WAIT(0); }
        __syncthreads();
        if (i + NSTAGE - 1 < niter) load_stage((i + NSTAGE - 1) % NSTAGE, i + NSTAGE - 1);

        uint32_t base = sbase + (uint32_t)(i % NSTAGE) * STG;
#pragma unroll
        for (int ks = 0; ks < 4; ++ks) {
            const uint32_t kb = (uint32_t)ks * 32;
            uint32_t ah[2][4], bh[4][4];
#pragma unroll
            for (int ni = 0; ni < 4; ++ni)
                ldsm_x4(bh[ni], base + T_BH + b_rt[ni] + ((b_cb + kb) ^ b_xr[ni]));
#pragma unroll
            for (int ti = 0; ti < 2; ++ti)
                ldsm_x4(ah[ti], base + T_AH + a_rt[ti] + ((a_cb + kb) ^ a_xr[ti]));

#pragma unroll
            for (int mi = 0; mi < 2; ++mi)
#pragma unroll
                for (int ni = 0; ni < 4; ++ni) {
                    MMA_F16(acc[mi][2*ni],   ah[mi], bh[ni][0], bh[ni][1]);
                    MMA_F16(acc[mi][2*ni+1], ah[mi], bh[ni][2], bh[ni][3]);
                }
        }
        __syncthreads();
    }

    // ---- epilogue ----
#pragma unroll
    for (int mi = 0; mi < 2; ++mi) {
        int gm = m0 + wm + mi * 16 + (lane >> 2);
#pragma unroll
        for (int ni = 0; ni < 8; ++ni) {
            int gn = n0 + wn + ni * 8 + (lane & 3) * 2;
            if constexpr (sizeof(OutT) == 4) {
                float2 v0 = make_float2(acc[mi][ni][0], acc[mi][ni][1]);
                float2 v1 = make_float2(acc[mi][ni][2], acc[mi][ni][3]);
                *(float2*)((float*)C + (size_t)gm * ldc + gn) = v0;
                *(float2*)((float*)C + (size_t)(gm + 8) * ldc + gn) = v1;
            } else {
                __half2 h0; h0.x = __float2half_rn(acc[mi][ni][0]); h0.y = __float2half_rn(acc[mi][ni][1]);
                __half2 h1; h1.x = __float2half_rn(acc[mi][ni][2]); h1.y = __float2half_rn(acc[mi][ni][3]);
                *(__half2*)((__half*)C + (size_t)gm * ldc + gn) = h0;
                *(__half2*)((__half*)C + (size_t)(gm + 8) * ldc + gn) = h1;
            }
        }
    }
}

// ---------------- fused RoPE + 16x16 head-attn, 2 tokens per block ----------------
#define PAD 65
__global__ __launch_bounds__(256) void attn_kernel()
{
    __shared__ float q [2][HH][PAD];
    __shared__ float kk[2][HH][PAD];
    __shared__ float vv[2][HH][PAD];
    __shared__ float sc[2][HH][17];
    __shared__ float cs[2][32], sn[2][32];

    const int tok0 = blockIdx.x * 2;
    const int tid = threadIdx.x;

    if (tid < 64) {
        int tk = tid >> 5, d2 = tid & 31;
        int t = (tok0 + tk) & (TT - 1);
        cs[tk][d2] = g_cos[t*32 + d2];
        sn[tk][d2] = g_sin[t*32 + d2];
    }

    // load 2 tokens x 3072 halfs = 768 float4, 3 per thread, coalesced
    const float4* base = (const float4*)(g_qkv + (size_t)tok0 * QKVC);
#pragma unroll
    for (int r = 0; r < 3; ++r) {
        int id = r * 256 + tid;          // 0..767
        float4 raw = base[id];
        int tk = id >= 384;
        int f  = id - tk * 384;          // 0..383
        int s  = f >> 7;                 // 0=q 1=k 2=v
        int h  = (f >> 3) & 15;
        int d0 = (f & 7) * 8;
        float* dst = (s == 0 ? &q[tk][h][d0] : s == 1 ? &kk[tk][h][d0] : &vv[tk][h][d0]);
        const __half2* hp = (const __half2*)&raw;
#pragma unroll
        for (int j = 0; j < 4; ++j) {
            float2 fv = __half22float2(hp[j]);
            dst[2*j]   = fv.x;
            dst[2*j+1] = fv.y;
        }
    }
    __syncthreads();

    // RoPE: 2 tokens x (q,k) x 16 heads x 32 pairs = 2048 / 256 = 8 per thread
#pragma unroll
    for (int r = 0; r < 8; ++r) {
        int idx = tid + 256 * r;         // 0..2047
        int tk = idx >> 10;
        int which = (idx >> 9) & 1;
        int h = (idx >> 5) & 15;
        int d2 = idx & 31;
        float c = cs[tk][d2], s = sn[tk][d2];
        float* buf = which ? &kk[tk][0][0] : &q[tk][0][0];
        float x1 = buf[h*PAD + 2*d2];
        float x2 = buf[h*PAD + 2*d2 + 1];
        buf[h*PAD + 2*d2]     = x1*c - x2*s;
        buf[h*PAD + 2*d2 + 1] = x2*c + x1*s;
    }
    __syncthreads();

    // scores: 2 x 256 (hq,hk) pairs = 512 / 256 = 2 per thread
#pragma unroll
    for (int r = 0; r < 2; ++r) {
        int idx = tid + 256 * r;
        int tk = idx >> 8;
        int hq = (idx >> 4) & 15, hk = idx & 15;
        float s = 0.f;
#pragma unroll
        for (int d = 0; d < DD; ++d) s = fmaf(q[tk][hq][d], kk[tk][hk][d], s);
        sc[tk][hq][hk] = s * 0.125f;
    }
    __syncthreads();

    // softmax: 32 rows (2 tokens x 16)
    if (tid < 32) {
        int tk = tid >> 4, row = tid & 15;
        float mx = -1e30f;
#pragma unroll
        for (int j = 0; j < 16; ++j) mx = fmaxf(mx, sc[tk][row][j]);
        float sum = 0.f;
#pragma unroll
        for (int j = 0; j < 16; ++j) { float e = expf(sc[tk][row][j] - mx); sc[tk][row][j] = e; sum += e; }
        float inv = 1.f / sum;
#pragma unroll
        for (int j = 0; j < 16; ++j) sc[tk][row][j] *= inv;
    }
    __syncthreads();

    // out + scrambled fp16 store: 2 x 1024 / 256 = 8 per thread
#pragma unroll
    for (int r = 0; r < 8; ++r) {
        int idx = tid + 256 * r;
        int tk = idx >> 10;
        int hq = (idx >> 6) & 15, d = idx & 63;
        float o = 0.f;
#pragma unroll
        for (int hk = 0; hk < 16; ++hk) o = fmaf(sc[tk][hq][hk], vv[tk][hk][d], o);
        int tg = tok0 + tk;
        int b = tg >> 13, t = tg & (TT - 1);
        size_t obase = ((size_t)b * TT + (t >> 4)) * (size_t)CC + (size_t)(t & 15) * DD;
        g_sh[obase + (size_t)hq * 512 * CC + d] = __float2half_rn(o);
    }
}

// ---------------------------------------------------------------------------
extern "C" void kernel_launch(void* const* d_in, const int* in_sizes, int n_in,
                              void* d_out, int out_size)
{
    const float* x    = (const float*)d_in[0];
    const float* Wqkv = (const float*)d_in[1];
    const float* Wout = (const float*)d_in[2];
    float* out = (float*)d_out;

    __half *qkv_p, *xh, *sh, *wqh, *woh;
    cudaGetSymbolAddress((void**)&qkv_p, g_qkv);
    cudaGetSymbolAddress((void**)&xh, g_xh);
    cudaGetSymbolAddress((void**)&sh, g_sh);
    cudaGetSymbolAddress((void**)&wqh, g_wqh);
    cudaGetSymbolAddress((void**)&woh, g_woh);

    cudaFuncSetAttribute(gemm_mma<__half>, cudaFuncAttributeMaxDynamicSharedMemorySize, GEMM_DYN);
    cudaFuncSetAttribute(gemm_mma<float>,  cudaFuncAttributeMaxDynamicSharedMemorySize, GEMM_DYN);

    rope_table_kernel<<<(TT*32 + 255) / 256, 256>>>();
    cvt_kernel<<<(MTOT*CC/4 + 255) / 256, 256>>>((const float4*)x,    (__half2*)xh,  MTOT*CC/4);
    cvt_kernel<<<(QKVC*CC/4 + 255) / 256, 256>>>((const float4*)Wqkv, (__half2*)wqh, QKVC*CC/4);
    cvt_kernel<<<(CC*CC/4   + 255) / 256, 256>>>((const float4*)Wout, (__half2*)woh, CC*CC/4);

    // GEMM1: qkv(fp16) = x @ Wqkv^T  (M=16384, N=3072, K=1024)
    {
        dim3 grid(QKVC / BN, MTOT / BM);
        gemm_mma<__half><<<grid, 256, GEMM_DYN>>>(xh, wqh, qkv_p, QKVC, CC);
    }

    // fused RoPE + head-attention + scramble (2 tokens/block)
    attn_kernel<<<MTOT / 2, 256>>>();

    // GEMM2: out = scr @ Wout^T (M=16384, N=1024, K=1024)
    {
        dim3 grid(CC / BN, MTOT / BM);
        gemm_mma<float><<<grid, 256, GEMM_DYN>>>(sh, woh, out, CC, CC);
    }
}

// round 9
// speedup vs baseline: 4.3407x; 1.0704x over previous
#include <cuda_runtime.h>
#include <cuda_fp16.h>
#include <math.h>
#include <stdint.h>

#define BB 2
#define TT 8192
#define CC 1024
#define HH 16
#define DD 64
#define MTOT (BB*TT)        // 16384
#define QKVC (3*CC)         // 3072

// ---------------- device scratch ----------------
__device__ __half g_qkv[(size_t)MTOT * QKVC];      // 96 MB fp16
__device__ __half g_xh[(size_t)MTOT * CC];
__device__ __half g_sh[(size_t)MTOT * CC];
__device__ __half g_wqh[(size_t)QKVC * CC];
__device__ __half g_woh[(size_t)CC * CC];
__device__ float g_cos[TT * 32];
__device__ float g_sin[TT * 32];

// ---------------- PTX helpers ----------------
__device__ __forceinline__ uint32_t smem_u32(const void* p) {
    uint32_t a;
    asm("{ .reg .u64 t; cvta.to.shared.u64 t, %1; cvt.u32.u64 %0, t; }" : "=r"(a) : "l"(p));
    return a;
}
__device__ __forceinline__ void cp16(uint32_t s, const void* g) {
    asm volatile("cp.async.cg.shared.global [%0], [%1], 16;" :: "r"(s), "l"(g));
}
#define CP_COMMIT() asm volatile("cp.async.commit_group;" ::: "memory")
#define CP_WAIT(n)  asm volatile("cp.async.wait_group %0;" :: "n"(n) : "memory")

__device__ __forceinline__ void ldsm_x4(uint32_t* r, uint32_t addr) {
    asm volatile("ldmatrix.sync.aligned.m8n8.x4.shared.b16 {%0,%1,%2,%3}, [%4];"
                 : "=r"(r[0]), "=r"(r[1]), "=r"(r[2]), "=r"(r[3]) : "r"(addr));
}
#define MMA_F16(d, a, b0, b1) \
    asm volatile("mma.sync.aligned.m16n8k16.row.col.f32.f16.f16.f32 " \
                 "{%0,%1,%2,%3}, {%4,%5,%6,%7}, {%8,%9}, {%0,%1,%2,%3};" \
                 : "+f"((d)[0]), "+f"((d)[1]), "+f"((d)[2]), "+f"((d)[3]) \
                 : "r"((a)[0]), "r"((a)[1]), "r"((a)[2]), "r"((a)[3]), \
                   "r"(b0), "r"(b1))

// ---------------- small kernels ----------------
__global__ void rope_table_kernel() {
    int idx = blockIdx.x * blockDim.x + threadIdx.x;
    if (idx >= TT * 32) return;
    int t = idx >> 5, d2 = idx & 31;
    float invf = (float)pow(10000.0, -(double)d2 / 32.0);
    float ang = __fmul_rn((float)t, invf);
    g_cos[idx] = (float)cos((double)ang);
    g_sin[idx] = (float)sin((double)ang);
}

__global__ void cvt_kernel(const float4* __restrict__ in,
                           __half2* __restrict__ hi, int n4) {
    int i = blockIdx.x * blockDim.x + threadIdx.x;
    if (i >= n4) return;
    float4 v = in[i];
    __half2 H0; H0.x = __float2half_rn(v.x); H0.y = __float2half_rn(v.y);
    __half2 H1; H1.x = __float2half_rn(v.z); H1.y = __float2half_rn(v.w);
    hi[2*i] = H0; hi[2*i+1] = H1;
}

// ---------------- fp16 GEMM (NT): C[m,n] = sum_k A[m,k]*B[n,k] ----------------
// CTA tile 128x256, warp tile 64x64 (2x4 warp grid), BK=64, 4-stage cp.async.
#define BM 128
#define BN 256
#define BKQ 64
#define T_A 0
#define T_B (16*1024)
#define STG  (48*1024)
#define NSTAGE 4
#define GEMM_DYN (NSTAGE*STG + 1024)

extern __shared__ char dynsmem[];

template <typename OutT>
__global__ __launch_bounds__(256, 1) void gemm_mma(
    const __half* __restrict__ Ah,
    const __half* __restrict__ Bh,
    OutT* __restrict__ C, int ldc, int K)
{
    const int tid  = threadIdx.x;
    const int wid  = tid >> 5;
    const int lane = tid & 31;
    const int m0 = blockIdx.y * BM;
    const int n0 = blockIdx.x * BN;
    const int wm = (wid >> 2) * 64;   // 2 warp-rows
    const int wn = (wid & 3) * 64;    // 4 warp-cols

    uint32_t sbase = (smem_u32(dynsmem) + 1023u) & ~1023u;

    // ---- loaders: A rows 0..127 (4 chunks/thread), B rows 0..255 (8 chunks/thread)
    const int lrow = tid >> 1;
    const int lc4  = (tid & 1) * 4;
    uint32_t soffA[4], soffB0[4], soffB1[4];
#pragma unroll
    for (int c = 0; c < 4; ++c) {
        uint32_t offA = (uint32_t)lrow * 128 + (uint32_t)(lc4 + c) * 16;
        soffA[c] = offA ^ ((offA >> 3) & 0x70);
        soffB0[c] = soffA[c];
        uint32_t offB1 = (uint32_t)(lrow + 128) * 128 + (uint32_t)(lc4 + c) * 16;
        soffB1[c] = offB1 ^ ((offB1 >> 3) & 0x70);
    }
    const __half* gA  = Ah + (size_t)(m0 + lrow) * K + lc4 * 8;
    const __half* gB0 = Bh + (size_t)(n0 + lrow) * K + lc4 * 8;
    const __half* gB1 = Bh + (size_t)(n0 + 128 + lrow) * K + lc4 * 8;

    auto load_stage = [&](int stage, int iter) {
        uint32_t st = sbase + (uint32_t)stage * STG;
        const int k0 = iter * BKQ;
#pragma unroll
        for (int c = 0; c < 4; ++c) {
            cp16(st + T_A + soffA[c],  gA  + k0 + c * 8);
            cp16(st + T_B + soffB0[c], gB0 + k0 + c * 8);
            cp16(st + T_B + soffB1[c], gB1 + k0 + c * 8);
        }
        CP_COMMIT();
    };

    // ---- ldmatrix address precompute ----
    uint32_t a_rt[4], a_xr[4];
#pragma unroll
    for (int ti = 0; ti < 4; ++ti) {
        int r = wm + ti * 16 + (lane & 15);
        a_rt[ti] = (uint32_t)r * 128;
        a_xr[ti] = (uint32_t)(r & 7) << 4;
    }
    const uint32_t a_cb = (uint32_t)(lane >> 4) * 16;
    uint32_t b_rt[4], b_xr[4];
#pragma unroll
    for (int ni = 0; ni < 4; ++ni) {
        int r = wn + ni * 16 + (lane & 7) + (lane >> 4) * 8;
        b_rt[ni] = (uint32_t)r * 128;
        b_xr[ni] = (uint32_t)(r & 7) << 4;
    }
    const uint32_t b_cb = (uint32_t)((lane >> 3) & 1) * 16;

    float acc[4][8][4];
#pragma unroll
    for (int i = 0; i < 4; ++i)
#pragma unroll
        for (int j = 0; j < 8; ++j)
#pragma unroll
            for (int q = 0; q < 4; ++q) acc[i][j][q] = 0.f;

    const int niter = K / BKQ;   // 16

#pragma unroll
    for (int s = 0; s < NSTAGE - 1; ++s) load_stage(s, s);

    for (int i = 0; i < niter; ++i) {
        if (i + NSTAGE - 1 < niter) { CP_WAIT(NSTAGE - 2); } else { CP_WAIT(0); }
        __syncthreads();
        if (i + NSTAGE - 1 < niter) load_stage((i + NSTAGE - 1) % NSTAGE, i + NSTAGE - 1);

        uint32_t base = sbase + (uint32_t)(i % NSTAGE) * STG;
#pragma unroll
        for (int ks = 0; ks < 4; ++ks) {
            const uint32_t kb = (uint32_t)ks * 32;
            uint32_t ah[4][4], bh[4][4];
#pragma unroll
            for (int ni = 0; ni < 4; ++ni)
                ldsm_x4(bh[ni], base + T_B + b_rt[ni] + ((b_cb + kb) ^ b_xr[ni]));
#pragma unroll
            for (int ti = 0; ti < 4; ++ti)
                ldsm_x4(ah[ti], base + T_A + a_rt[ti] + ((a_cb + kb) ^ a_xr[ti]));

#pragma unroll
            for (int mi = 0; mi < 4; ++mi)
#pragma unroll
                for (int ni = 0; ni < 4; ++ni) {
                    MMA_F16(acc[mi][2*ni],   ah[mi], bh[ni][0], bh[ni][1]);
                    MMA_F16(acc[mi][2*ni+1], ah[mi], bh[ni][2], bh[ni][3]);
                }
        }
        __syncthreads();
    }

    // ---- epilogue ----
#pragma unroll
    for (int mi = 0; mi < 4; ++mi) {
        int gm = m0 + wm + mi * 16 + (lane >> 2);
#pragma unroll
        for (int ni = 0; ni < 8; ++ni) {
            int gn = n0 + wn + ni * 8 + (lane & 3) * 2;
            if constexpr (sizeof(OutT) == 4) {
                float2 v0 = make_float2(acc[mi][ni][0], acc[mi][ni][1]);
                float2 v1 = make_float2(acc[mi][ni][2], acc[mi][ni][3]);
                *(float2*)((float*)C + (size_t)gm * ldc + gn) = v0;
                *(float2*)((float*)C + (size_t)(gm + 8) * ldc + gn) = v1;
            } else {
                __half2 h0; h0.x = __float2half_rn(acc[mi][ni][0]); h0.y = __float2half_rn(acc[mi][ni][1]);
                __half2 h1; h1.x = __float2half_rn(acc[mi][ni][2]); h1.y = __float2half_rn(acc[mi][ni][3]);
                *(__half2*)((__half*)C + (size_t)gm * ldc + gn) = h0;
                *(__half2*)((__half*)C + (size_t)(gm + 8) * ldc + gn) = h1;
            }
        }
    }
}

// ---------------- fused RoPE + 16x16 head-attn, 2 tokens per block ----------------
#define PAD 65
__global__ __launch_bounds__(256) void attn_kernel()
{
    __shared__ float q [2][HH][PAD];
    __shared__ float kk[2][HH][PAD];
    __shared__ float vv[2][HH][PAD];
    __shared__ float sc[2][HH][17];
    __shared__ float cs[2][32], sn[2][32];

    const int tok0 = blockIdx.x * 2;
    const int tid = threadIdx.x;

    if (tid < 64) {
        int tk = tid >> 5, d2 = tid & 31;
        int t = (tok0 + tk) & (TT - 1);
        cs[tk][d2] = g_cos[t*32 + d2];
        sn[tk][d2] = g_sin[t*32 + d2];
    }

    const float4* base = (const float4*)(g_qkv + (size_t)tok0 * QKVC);
#pragma unroll
    for (int r = 0; r < 3; ++r) {
        int id = r * 256 + tid;
        float4 raw = base[id];
        int tk = id >= 384;
        int f  = id - tk * 384;
        int s  = f >> 7;
        int h  = (f >> 3) & 15;
        int d0 = (f & 7) * 8;
        float* dst = (s == 0 ? &q[tk][h][d0] : s == 1 ? &kk[tk][h][d0] : &vv[tk][h][d0]);
        const __half2* hp = (const __half2*)&raw;
#pragma unroll
        for (int j = 0; j < 4; ++j) {
            float2 fv = __half22float2(hp[j]);
            dst[2*j]   = fv.x;
            dst[2*j+1] = fv.y;
        }
    }
    __syncthreads();

#pragma unroll
    for (int r = 0; r < 8; ++r) {
        int idx = tid + 256 * r;
        int tk = idx >> 10;
        int which = (idx >> 9) & 1;
        int h = (idx >> 5) & 15;
        int d2 = idx & 31;
        float c = cs[tk][d2], s = sn[tk][d2];
        float* buf = which ? &kk[tk][0][0] : &q[tk][0][0];
        float x1 = buf[h*PAD + 2*d2];
        float x2 = buf[h*PAD + 2*d2 + 1];
        buf[h*PAD + 2*d2]     = x1*c - x2*s;
        buf[h*PAD + 2*d2 + 1] = x2*c + x1*s;
    }
    __syncthreads();

#pragma unroll
    for (int r = 0; r < 2; ++r) {
        int idx = tid + 256 * r;
        int tk = idx >> 8;
        int hq = (idx >> 4) & 15, hk = idx & 15;
        float s = 0.f;
#pragma unroll
        for (int d = 0; d < DD; ++d) s = fmaf(q[tk][hq][d], kk[tk][hk][d], s);
        sc[tk][hq][hk] = s * 0.125f;
    }
    __syncthreads();

    if (tid < 32) {
        int tk = tid >> 4, row = tid & 15;
        float mx = -1e30f;
#pragma unroll
        for (int j = 0; j < 16; ++j) mx = fmaxf(mx, sc[tk][row][j]);
        float sum = 0.f;
#pragma unroll
        for (int j = 0; j < 16; ++j) { float e = expf(sc[tk][row][j] - mx); sc[tk][row][j] = e; sum += e; }
        float inv = 1.f / sum;
#pragma unroll
        for (int j = 0; j < 16; ++j) sc[tk][row][j] *= inv;
    }
    __syncthreads();

#pragma unroll
    for (int r = 0; r < 8; ++r) {
        int idx = tid + 256 * r;
        int tk = idx >> 10;
        int hq = (idx >> 6) & 15, d = idx & 63;
        float o = 0.f;
#pragma unroll
        for (int hk = 0; hk < 16; ++hk) o = fmaf(sc[tk][hq][hk], vv[tk][hk][d], o);
        int tg = tok0 + tk;
        int b = tg >> 13, t = tg & (TT - 1);
        size_t obase = ((size_t)b * TT + (t >> 4)) * (size_t)CC + (size_t)(t & 15) * DD;
        g_sh[obase + (size_t)hq * 512 * CC + d] = __float2half_rn(o);
    }
}

// ---------------------------------------------------------------------------
extern "C" void kernel_launch(void* const* d_in, const int* in_sizes, int n_in,
                              void* d_out, int out_size)
{
    const float* x    = (const float*)d_in[0];
    const float* Wqkv = (const float*)d_in[1];
    const float* Wout = (const float*)d_in[2];
    float* out = (float*)d_out;

    __half *qkv_p, *xh, *sh, *wqh, *woh;
    cudaGetSymbolAddress((void**)&qkv_p, g_qkv);
    cudaGetSymbolAddress((void**)&xh, g_xh);
    cudaGetSymbolAddress((void**)&sh, g_sh);
    cudaGetSymbolAddress((void**)&wqh, g_wqh);
    cudaGetSymbolAddress((void**)&woh, g_woh);

    cudaFuncSetAttribute(gemm_mma<__half>, cudaFuncAttributeMaxDynamicSharedMemorySize, GEMM_DYN);
    cudaFuncSetAttribute(gemm_mma<float>,  cudaFuncAttributeMaxDynamicSharedMemorySize, GEMM_DYN);

    rope_table_kernel<<<(TT*32 + 255) / 256, 256>>>();
    cvt_kernel<<<(MTOT*CC/4 + 255) / 256, 256>>>((const float4*)x,    (__half2*)xh,  MTOT*CC/4);
    cvt_kernel<<<(QKVC*CC/4 + 255) / 256, 256>>>((const float4*)Wqkv, (__half2*)wqh, QKVC*CC/4);
    cvt_kernel<<<(CC*CC/4   + 255) / 256, 256>>>((const float4*)Wout, (__half2*)woh, CC*CC/4);

    // GEMM1: qkv(fp16) = x @ Wqkv^T  (M=16384, N=3072, K=1024)
    {
        dim3 grid(QKVC / BN, MTOT / BM);
        gemm_mma<__half><<<grid, 256, GEMM_DYN>>>(xh, wqh, qkv_p, QKVC, CC);
    }

    // fused RoPE + head-attention + scramble (2 tokens/block)
    attn_kernel<<<MTOT / 2, 256>>>();

    // GEMM2: out = scr @ Wout^T (M=16384, N=1024, K=1024)
    {
        dim3 grid(CC / BN, MTOT / BM);
        gemm_mma<float><<<grid, 256, GEMM_DYN>>>(sh, woh, out, CC, CC);
    }
}

// round 10
// speedup vs baseline: 4.4110x; 1.0162x over previous
#include <cuda_runtime.h>
#include <cuda_fp16.h>
#include <math.h>
#include <stdint.h>

#define BB 2
#define TT 8192
#define CC 1024
#define HH 16
#define DD 64
#define MTOT (BB*TT)        // 16384
#define QKVC (3*CC)         // 3072

// ---------------- device scratch ----------------
__device__ __half g_qkv[(size_t)MTOT * QKVC];      // 96 MB fp16
__device__ __half g_xh[(size_t)MTOT * CC];
__device__ __half g_sh[(size_t)MTOT * CC];
__device__ __half g_wqh[(size_t)QKVC * CC];
__device__ __half g_woh[(size_t)CC * CC];
__device__ float g_cos[TT * 32];
__device__ float g_sin[TT * 32];

// ---------------- PTX helpers ----------------
__device__ __forceinline__ uint32_t smem_u32(const void* p) {
    uint32_t a;
    asm("{ .reg .u64 t; cvta.to.shared.u64 t, %1; cvt.u32.u64 %0, t; }" : "=r"(a) : "l"(p));
    return a;
}
__device__ __forceinline__ void cp16(uint32_t s, const void* g) {
    asm volatile("cp.async.cg.shared.global [%0], [%1], 16;" :: "r"(s), "l"(g));
}
#define CP_COMMIT() asm volatile("cp.async.commit_group;" ::: "memory")
#define CP_WAIT(n)  asm volatile("cp.async.wait_group %0;" :: "n"(n) : "memory")

__device__ __forceinline__ void ldsm_x4(uint32_t* r, uint32_t addr) {
    asm volatile("ldmatrix.sync.aligned.m8n8.x4.shared.b16 {%0,%1,%2,%3}, [%4];"
                 : "=r"(r[0]), "=r"(r[1]), "=r"(r[2]), "=r"(r[3]) : "r"(addr));
}
#define MMA_F16(d, a, b0, b1) \
    asm volatile("mma.sync.aligned.m16n8k16.row.col.f32.f16.f16.f32 " \
                 "{%0,%1,%2,%3}, {%4,%5,%6,%7}, {%8,%9}, {%0,%1,%2,%3};" \
                 : "+f"((d)[0]), "+f"((d)[1]), "+f"((d)[2]), "+f"((d)[3]) \
                 : "r"((a)[0]), "r"((a)[1]), "r"((a)[2]), "r"((a)[3]), \
                   "r"(b0), "r"(b1))

// ---------------- small kernels ----------------
__global__ void rope_table_kernel() {
    int idx = blockIdx.x * blockDim.x + threadIdx.x;
    if (idx >= TT * 32) return;
    int t = idx >> 5, d2 = idx & 31;
    float invf = (float)pow(10000.0, -(double)d2 / 32.0);
    float ang = __fmul_rn((float)t, invf);
    g_cos[idx] = (float)cos((double)ang);
    g_sin[idx] = (float)sin((double)ang);
}

__global__ void cvt_kernel(const float4* __restrict__ in,
                           __half2* __restrict__ hi, int n4) {
    int i = blockIdx.x * blockDim.x + threadIdx.x;
    if (i >= n4) return;
    float4 v = in[i];
    __half2 H0; H0.x = __float2half_rn(v.x); H0.y = __float2half_rn(v.y);
    __half2 H1; H1.x = __float2half_rn(v.z); H1.y = __float2half_rn(v.w);
    hi[2*i] = H0; hi[2*i+1] = H1;
}

// ---------------- persistent fp16 GEMM (NT): C[m,n] = sum_k A[m,k]*B[n,k] ----------------
// CTA tile 128x256, warp tile 64x64 (2x4 warps), BK=64, 4-stage cp.async ring
// that flows continuously across tiles (prologue once per CTA; epilogue of
// tile j overlaps the in-flight loads of tile j+1). One barrier per iter.
#define BM 128
#define BN 256
#define BKQ 64
#define KITER 16            // K(=1024)/BKQ, fixed for both GEMMs
#define T_A 0
#define T_B (16*1024)
#define STG  (48*1024)
#define NSTAGE 4
#define GEMM_DYN (NSTAGE*STG + 1024)

extern __shared__ char dynsmem[];

template <typename OutT>
__global__ __launch_bounds__(256, 1) void gemm_mma(
    const __half* __restrict__ Ah,
    const __half* __restrict__ Bh,
    OutT* __restrict__ C, int ldc, int K, int ntN, int ntiles)
{
    const int tid  = threadIdx.x;
    const int wid  = tid >> 5;
    const int lane = tid & 31;
    const int wm = (wid >> 2) * 64;
    const int wn = (wid & 3) * 64;
    const int bx = blockIdx.x;
    const int grid = gridDim.x;

    // number of tiles this CTA owns; iters = tiles * KITER
    const int my_nt = (ntiles - 1 - bx) / grid + 1;   // bx < ntiles always here
    const int my_iters = my_nt * KITER;

    uint32_t sbase = (smem_u32(dynsmem) + 1023u) & ~1023u;

    // ---- loader setup: per-thread row & swizzled smem offsets ----
    const int lrow = tid >> 1;
    const int lc4  = (tid & 1) * 4;
    uint32_t soffA[4], soffB1[4];
#pragma unroll
    for (int c = 0; c < 4; ++c) {
        uint32_t offA = (uint32_t)lrow * 128 + (uint32_t)(lc4 + c) * 16;
        soffA[c] = offA ^ ((offA >> 3) & 0x70);
        uint32_t offB1 = (uint32_t)(lrow + 128) * 128 + (uint32_t)(lc4 + c) * 16;
        soffB1[c] = offB1 ^ ((offB1 >> 3) & 0x70);
    }
    const int gcol = lc4 * 8;   // element column within the 64-wide K chunk

    // load virtual iteration li (tile j = li/KITER, k-chunk = li%KITER)
    auto load_stage = [&](int li) {
        int j  = li >> 4;
        int kk = li & 15;
        int tile = bx + j * grid;
        int tm = tile / ntN;
        int tn = tile - tm * ntN;
        const __half* gA  = Ah + (size_t)(tm * BM + lrow) * K + kk * BKQ + gcol;
        const __half* gB0 = Bh + (size_t)(tn * BN + lrow) * K + kk * BKQ + gcol;
        const __half* gB1 = gB0 + (size_t)128 * K;
        uint32_t st = sbase + (uint32_t)(li & (NSTAGE - 1)) * STG;
#pragma unroll
        for (int c = 0; c < 4; ++c) {
            cp16(st + T_A + soffA[c],  gA  + c * 8);
            cp16(st + T_B + soffA[c],  gB0 + c * 8);
            cp16(st + T_B + soffB1[c], gB1 + c * 8);
        }
        CP_COMMIT();
    };

    // ---- ldmatrix address precompute (tile-invariant) ----
    uint32_t a_rt[4], a_xr[4];
#pragma unroll
    for (int ti = 0; ti < 4; ++ti) {
        int r = wm + ti * 16 + (lane & 15);
        a_rt[ti] = (uint32_t)r * 128;
        a_xr[ti] = (uint32_t)(r & 7) << 4;
    }
    const uint32_t a_cb = (uint32_t)(lane >> 4) * 16;
    uint32_t b_rt[4], b_xr[4];
#pragma unroll
    for (int ni = 0; ni < 4; ++ni) {
        int r = wn + ni * 16 + (lane & 7) + (lane >> 4) * 8;
        b_rt[ni] = (uint32_t)r * 128;
        b_xr[ni] = (uint32_t)(r & 7) << 4;
    }
    const uint32_t b_cb = (uint32_t)((lane >> 3) & 1) * 16;

    float acc[4][8][4];
#pragma unroll
    for (int i = 0; i < 4; ++i)
#pragma unroll
        for (int j = 0; j < 8; ++j)
#pragma unroll
            for (int q = 0; q < 4; ++q) acc[i][j][q] = 0.f;

    // ---- prologue: fill NSTAGE-1 stages once ----
#pragma unroll
    for (int s = 0; s < NSTAGE - 1; ++s) load_stage(s);

    // ---- continuous mainloop over all owned tiles ----
    for (int ci = 0; ci < my_iters; ++ci) {
        if (ci + NSTAGE - 1 < my_iters) {
            CP_WAIT(NSTAGE - 2);
            __syncthreads();
            load_stage(ci + NSTAGE - 1);
        } else {
            CP_WAIT(0);
            __syncthreads();
        }

        uint32_t base = sbase + (uint32_t)(ci & (NSTAGE - 1)) * STG;
#pragma unroll
        for (int ks = 0; ks < 4; ++ks) {
            const uint32_t kb = (uint32_t)ks * 32;
            uint32_t ah[4][4], bh[4][4];
#pragma unroll
            for (int ni = 0; ni < 4; ++ni)
                ldsm_x4(bh[ni], base + T_B + b_rt[ni] + ((b_cb + kb) ^ b_xr[ni]));
#pragma unroll
            for (int ti = 0; ti < 4; ++ti)
                ldsm_x4(ah[ti], base + T_A + a_rt[ti] + ((a_cb + kb) ^ a_xr[ti]));

#pragma unroll
            for (int mi = 0; mi < 4; ++mi)
#pragma unroll
                for (int ni = 0; ni < 4; ++ni) {
                    MMA_F16(acc[mi][2*ni],   ah[mi], bh[ni][0], bh[ni][1]);
                    MMA_F16(acc[mi][2*ni+1], ah[mi], bh[ni][2], bh[ni][3]);
                }
        }

        // ---- tile finished: epilogue overlapped with next tile's loads ----
        if ((ci & (KITER - 1)) == KITER - 1) {
            int tile = bx + (ci >> 4) * grid;
            int tm = tile / ntN;
            int tn = tile - tm * ntN;
#pragma unroll
            for (int mi = 0; mi < 4; ++mi) {
                int gm = tm * BM + wm + mi * 16 + (lane >> 2);
#pragma unroll
                for (int ni = 0; ni < 8; ++ni) {
                    int gn = tn * BN + wn + ni * 8 + (lane & 3) * 2;
                    if constexpr (sizeof(OutT) == 4) {
                        float2 v0 = make_float2(acc[mi][ni][0], acc[mi][ni][1]);
                        float2 v1 = make_float2(acc[mi][ni][2], acc[mi][ni][3]);
                        *(float2*)((float*)C + (size_t)gm * ldc + gn) = v0;
                        *(float2*)((float*)C + (size_t)(gm + 8) * ldc + gn) = v1;
                    } else {
                        __half2 h0; h0.x = __float2half_rn(acc[mi][ni][0]); h0.y = __float2half_rn(acc[mi][ni][1]);
                        __half2 h1; h1.x = __float2half_rn(acc[mi][ni][2]); h1.y = __float2half_rn(acc[mi][ni][3]);
                        *(__half2*)((__half*)C + (size_t)gm * ldc + gn) = h0;
                        *(__half2*)((__half*)C + (size_t)(gm + 8) * ldc + gn) = h1;
                    }
                }
            }
#pragma unroll
            for (int i = 0; i < 4; ++i)
#pragma unroll
                for (int j = 0; j < 8; ++j)
#pragma unroll
                    for (int q = 0; q < 4; ++q) acc[i][j][q] = 0.f;
        }
    }
}

// ---------------- fused RoPE + 16x16 head-attn, 2 tokens per block ----------------
#define PAD 65
__global__ __launch_bounds__(256) void attn_kernel()
{
    __shared__ float q [2][HH][PAD];
    __shared__ float kk[2][HH][PAD];
    __shared__ float vv[2][HH][PAD];
    __shared__ float sc[2][HH][17];
    __shared__ float cs[2][32], sn[2][32];

    const int tok0 = blockIdx.x * 2;
    const int tid = threadIdx.x;

    if (tid < 64) {
        int tk = tid >> 5, d2 = tid & 31;
        int t = (tok0 + tk) & (TT - 1);
        cs[tk][d2] = g_cos[t*32 + d2];
        sn[tk][d2] = g_sin[t*32 + d2];
    }

    const float4* base = (const float4*)(g_qkv + (size_t)tok0 * QKVC);
#pragma unroll
    for (int r = 0; r < 3; ++r) {
        int id = r * 256 + tid;
        float4 raw = base[id];
        int tk = id >= 384;
        int f  = id - tk * 384;
        int s  = f >> 7;
        int h  = (f >> 3) & 15;
        int d0 = (f & 7) * 8;
        float* dst = (s == 0 ? &q[tk][h][d0] : s == 1 ? &kk[tk][h][d0] : &vv[tk][h][d0]);
        const __half2* hp = (const __half2*)&raw;
#pragma unroll
        for (int j = 0; j < 4; ++j) {
            float2 fv = __half22float2(hp[j]);
            dst[2*j]   = fv.x;
            dst[2*j+1] = fv.y;
        }
    }
    __syncthreads();

#pragma unroll
    for (int r = 0; r < 8; ++r) {
        int idx = tid + 256 * r;
        int tk = idx >> 10;
        int which = (idx >> 9) & 1;
        int h = (idx >> 5) & 15;
        int d2 = idx & 31;
        float c = cs[tk][d2], s = sn[tk][d2];
        float* buf = which ? &kk[tk][0][0] : &q[tk][0][0];
        float x1 = buf[h*PAD + 2*d2];
        float x2 = buf[h*PAD + 2*d2 + 1];
        buf[h*PAD + 2*d2]     = x1*c - x2*s;
        buf[h*PAD + 2*d2 + 1] = x2*c + x1*s;
    }
    __syncthreads();

#pragma unroll
    for (int r = 0; r < 2; ++r) {
        int idx = tid + 256 * r;
        int tk = idx >> 8;
        int hq = (idx >> 4) & 15, hk = idx & 15;
        float s = 0.f;
#pragma unroll
        for (int d = 0; d < DD; ++d) s = fmaf(q[tk][hq][d], kk[tk][hk][d], s);
        sc[tk][hq][hk] = s * 0.125f;
    }
    __syncthreads();

    if (tid < 32) {
        int tk = tid >> 4, row = tid & 15;
        float mx = -1e30f;
#pragma unroll
        for (int j = 0; j < 16; ++j) mx = fmaxf(mx, sc[tk][row][j]);
        float sum = 0.f;
#pragma unroll
        for (int j = 0; j < 16; ++j) { float e = expf(sc[tk][row][j] - mx); sc[tk][row][j] = e; sum += e; }
        float inv = 1.f / sum;
#pragma unroll
        for (int j = 0; j < 16; ++j) sc[tk][row][j] *= inv;
    }
    __syncthreads();

#pragma unroll
    for (int r = 0; r < 8; ++r) {
        int idx = tid + 256 * r;
        int tk = idx >> 10;
        int hq = (idx >> 6) & 15, d = idx & 63;
        float o = 0.f;
#pragma unroll
        for (int hk = 0; hk < 16; ++hk) o = fmaf(sc[tk][hq][hk], vv[tk][hk][d], o);
        int tg = tok0 + tk;
        int b = tg >> 13, t = tg & (TT - 1);
        size_t obase = ((size_t)b * TT + (t >> 4)) * (size_t)CC + (size_t)(t & 15) * DD;
        g_sh[obase + (size_t)hq * 512 * CC + d] = __float2half_rn(o);
    }
}

// ---------------------------------------------------------------------------
extern "C" void kernel_launch(void* const* d_in, const int* in_sizes, int n_in,
                              void* d_out, int out_size)
{
    const float* x    = (const float*)d_in[0];
    const float* Wqkv = (const float*)d_in[1];
    const float* Wout = (const float*)d_in[2];
    float* out = (float*)d_out;

    __half *qkv_p, *xh, *sh, *wqh, *woh;
    cudaGetSymbolAddress((void**)&qkv_p, g_qkv);
    cudaGetSymbolAddress((void**)&xh, g_xh);
    cudaGetSymbolAddress((void**)&sh, g_sh);
    cudaGetSymbolAddress((void**)&wqh, g_wqh);
    cudaGetSymbolAddress((void**)&woh, g_woh);

    int nsm = 148;
    cudaDeviceGetAttribute(&nsm, cudaDevAttrMultiProcessorCount, 0);

    cudaFuncSetAttribute(gemm_mma<__half>, cudaFuncAttributeMaxDynamicSharedMemorySize, GEMM_DYN);
    cudaFuncSetAttribute(gemm_mma<float>,  cudaFuncAttributeMaxDynamicSharedMemorySize, GEMM_DYN);

    rope_table_kernel<<<(TT*32 + 255) / 256, 256>>>();
    cvt_kernel<<<(MTOT*CC/4 + 255) / 256, 256>>>((const float4*)x,    (__half2*)xh,  MTOT*CC/4);
    cvt_kernel<<<(QKVC*CC/4 + 255) / 256, 256>>>((const float4*)Wqkv, (__half2*)wqh, QKVC*CC/4);
    cvt_kernel<<<(CC*CC/4   + 255) / 256, 256>>>((const float4*)Wout, (__half2*)woh, CC*CC/4);

    // GEMM1: qkv(fp16) = x @ Wqkv^T  (M=16384, N=3072, K=1024) — 1536 tiles
    {
        int ntiles = (QKVC / BN) * (MTOT / BM);
        int grid = ntiles < nsm ? ntiles : nsm;
        gemm_mma<__half><<<grid, 256, GEMM_DYN>>>(xh, wqh, qkv_p, QKVC, CC, QKVC / BN, ntiles);
    }

    // fused RoPE + head-attention + scramble (2 tokens/block)
    attn_kernel<<<MTOT / 2, 256>>>();

    // GEMM2: out = scr @ Wout^T (M=16384, N=1024, K=1024) — 512 tiles
    {
        int ntiles = (CC / BN) * (MTOT / BM);
        int grid = ntiles < nsm ? ntiles : nsm;
        gemm_mma<float><<<grid, 256, GEMM_DYN>>>(sh, woh, out, CC, CC, CC / BN, ntiles);
    }
}

// round 11
// speedup vs baseline: 4.5648x; 1.0349x over previous
#include <cuda_runtime.h>
#include <cuda_fp16.h>
#include <math.h>
#include <stdint.h>

#define BB 2
#define TT 8192
#define CC 1024
#define HH 16
#define DD 64
#define MTOT (BB*TT)        // 16384
#define QKVC (3*CC)         // 3072

// ---------------- device scratch ----------------
__device__ __half g_qkv[(size_t)MTOT * QKVC];      // 96 MB fp16
__device__ __half g_xh[(size_t)MTOT * CC];
__device__ __half g_sh[(size_t)MTOT * CC];
__device__ __half g_wqh[(size_t)QKVC * CC];
__device__ __half g_woh[(size_t)CC * CC];
__device__ float g_cos[TT * 32];
__device__ float g_sin[TT * 32];

// ---------------- PTX helpers ----------------
__device__ __forceinline__ uint32_t smem_u32(const void* p) {
    uint32_t a;
    asm("{ .reg .u64 t; cvta.to.shared.u64 t, %1; cvt.u32.u64 %0, t; }" : "=r"(a) : "l"(p));
    return a;
}
__device__ __forceinline__ void cp16(uint32_t s, const void* g) {
    asm volatile("cp.async.cg.shared.global [%0], [%1], 16;" :: "r"(s), "l"(g));
}
#define CP_COMMIT() asm volatile("cp.async.commit_group;" ::: "memory")
#define CP_WAIT(n)  asm volatile("cp.async.wait_group %0;" :: "n"(n) : "memory")

__device__ __forceinline__ void ldsm_x4(uint32_t* r, uint32_t addr) {
    asm volatile("ldmatrix.sync.aligned.m8n8.x4.shared.b16 {%0,%1,%2,%3}, [%4];"
                 : "=r"(r[0]), "=r"(r[1]), "=r"(r[2]), "=r"(r[3]) : "r"(addr));
}
#define MMA_F16(d, a, b0, b1) \
    asm volatile("mma.sync.aligned.m16n8k16.row.col.f32.f16.f16.f32 " \
                 "{%0,%1,%2,%3}, {%4,%5,%6,%7}, {%8,%9}, {%0,%1,%2,%3};" \
                 : "+f"((d)[0]), "+f"((d)[1]), "+f"((d)[2]), "+f"((d)[3]) \
                 : "r"((a)[0]), "r"((a)[1]), "r"((a)[2]), "r"((a)[3]), \
                   "r"(b0), "r"(b1))

// ---------------- small kernels ----------------
__global__ void rope_table_kernel() {
    int idx = blockIdx.x * blockDim.x + threadIdx.x;
    if (idx >= TT * 32) return;
    int t = idx >> 5, d2 = idx & 31;
    float invf = (float)pow(10000.0, -(double)d2 / 32.0);
    float ang = __fmul_rn((float)t, invf);
    g_cos[idx] = (float)cos((double)ang);
    g_sin[idx] = (float)sin((double)ang);
}

// fp32 -> fp16, 4 coalesced float4 loads per thread (ILP=4).
// n4 must be a multiple of 1024 (true for all three tensors here).
__global__ void cvt_kernel(const float4* __restrict__ in,
                           __half2* __restrict__ hi, int n4) {
    int base = blockIdx.x * 1024 + threadIdx.x;
    float4 v[4];
#pragma unroll
    for (int k = 0; k < 4; ++k) v[k] = in[base + k * 256];
#pragma unroll
    for (int k = 0; k < 4; ++k) {
        int f = base + k * 256;
        __half2 a = __floats2half2_rn(v[k].x, v[k].y);
        __half2 b = __floats2half2_rn(v[k].z, v[k].w);
        uint2 pk; pk.x = *(uint32_t*)&a; pk.y = *(uint32_t*)&b;
        ((uint2*)hi)[f] = pk;
    }
}

// ---------------- persistent fp16 GEMM (NT): C[m,n] = sum_k A[m,k]*B[n,k] ----------------
// CTA tile 128x256, warp tile 64x64 (2x4 warps), BK=64, 4-stage cp.async ring.
// Pair-wise pipelining: one CP_WAIT + one __syncthreads per TWO K-iters;
// loads for iters e+2,e+3 issued together and overlap a full pair of compute.
#define BM 128
#define BN 256
#define BKQ 64
#define KITER 16            // K(=1024)/BKQ
#define T_A 0
#define T_B (16*1024)
#define STG  (48*1024)
#define NSTAGE 4
#define GEMM_DYN (NSTAGE*STG + 1024)

extern __shared__ char dynsmem[];

template <typename OutT>
__global__ __launch_bounds__(256, 1) void gemm_mma(
    const __half* __restrict__ Ah,
    const __half* __restrict__ Bh,
    OutT* __restrict__ C, int ldc, int K, int ntN, int ntiles)
{
    const int tid  = threadIdx.x;
    const int wid  = tid >> 5;
    const int lane = tid & 31;
    const int wm = (wid >> 2) * 64;
    const int wn = (wid & 3) * 64;
    const int bx = blockIdx.x;
    const int grid = gridDim.x;

    const int my_nt = (ntiles - 1 - bx) / grid + 1;
    const int my_iters = my_nt * KITER;

    uint32_t sbase = (smem_u32(dynsmem) + 1023u) & ~1023u;

    // ---- loader setup ----
    const int lrow = tid >> 1;
    const int lc4  = (tid & 1) * 4;
    uint32_t soffA[4], soffB1[4];
#pragma unroll
    for (int c = 0; c < 4; ++c) {
        uint32_t offA = (uint32_t)lrow * 128 + (uint32_t)(lc4 + c) * 16;
        soffA[c] = offA ^ ((offA >> 3) & 0x70);
        uint32_t offB1 = (uint32_t)(lrow + 128) * 128 + (uint32_t)(lc4 + c) * 16;
        soffB1[c] = offB1 ^ ((offB1 >> 3) & 0x70);
    }
    const int gcol = lc4 * 8;

    // incremental load cursor: division only at tile wrap (1/16 calls)
    int ld_tile = bx;
    int ld_tm = ld_tile / ntN;
    int ld_tn = ld_tile - ld_tm * ntN;
    int ld_kk = 0;
    int ld_stage = 0;

    auto load_stage = [&]() {
        const __half* gA  = Ah + (size_t)(ld_tm * BM + lrow) * K + ld_kk * BKQ + gcol;
        const __half* gB0 = Bh + (size_t)(ld_tn * BN + lrow) * K + ld_kk * BKQ + gcol;
        const __half* gB1 = gB0 + (size_t)128 * K;
        uint32_t st = sbase + (uint32_t)(ld_stage & (NSTAGE - 1)) * STG;
#pragma unroll
        for (int c = 0; c < 4; ++c) {
            cp16(st + T_A + soffA[c],  gA  + c * 8);
            cp16(st + T_B + soffA[c],  gB0 + c * 8);
            cp16(st + T_B + soffB1[c], gB1 + c * 8);
        }
        CP_COMMIT();
        ++ld_stage;
        if (++ld_kk == KITER) {
            ld_kk = 0;
            ld_tile += grid;
            ld_tm = ld_tile / ntN;
            ld_tn = ld_tile - ld_tm * ntN;
        }
    };

    // ---- ldmatrix address precompute (tile-invariant) ----
    uint32_t a_rt[4], a_xr[4];
#pragma unroll
    for (int ti = 0; ti < 4; ++ti) {
        int r = wm + ti * 16 + (lane & 15);
        a_rt[ti] = (uint32_t)r * 128;
        a_xr[ti] = (uint32_t)(r & 7) << 4;
    }
    const uint32_t a_cb = (uint32_t)(lane >> 4) * 16;
    uint32_t b_rt[4], b_xr[4];
#pragma unroll
    for (int ni = 0; ni < 4; ++ni) {
        int r = wn + ni * 16 + (lane & 7) + (lane >> 4) * 8;
        b_rt[ni] = (uint32_t)r * 128;
        b_xr[ni] = (uint32_t)(r & 7) << 4;
    }
    const uint32_t b_cb = (uint32_t)((lane >> 3) & 1) * 16;

    float acc[4][8][4];
#pragma unroll
    for (int i = 0; i < 4; ++i)
#pragma unroll
        for (int j = 0; j < 8; ++j)
#pragma unroll
            for (int q = 0; q < 4; ++q) acc[i][j][q] = 0.f;

    // ---- prologue: two stages in flight ----
    load_stage();
    if (1 < my_iters) load_stage();

    // ---- mainloop: wait + barrier once per pair of K-iters ----
    for (int ci = 0; ci < my_iters; ++ci) {
        if ((ci & 1) == 0) {
            CP_WAIT(0);                  // stages ci, ci+1 ready
            __syncthreads();             // stage buffers (ci+2,ci+3)&3 free
            if (ci + 2 < my_iters) load_stage();
            if (ci + 3 < my_iters) load_stage();
        }

        uint32_t base = sbase + (uint32_t)(ci & (NSTAGE - 1)) * STG;
#pragma unroll
        for (int ks = 0; ks < 4; ++ks) {
            const uint32_t kb = (uint32_t)ks * 32;
            uint32_t ah[4][4], bh[4][4];
#pragma unroll
            for (int ni = 0; ni < 4; ++ni)
                ldsm_x4(bh[ni], base + T_B + b_rt[ni] + ((b_cb + kb) ^ b_xr[ni]));
#pragma unroll
            for (int ti = 0; ti < 4; ++ti)
                ldsm_x4(ah[ti], base + T_A + a_rt[ti] + ((a_cb + kb) ^ a_xr[ti]));

#pragma unroll
            for (int mi = 0; mi < 4; ++mi)
#pragma unroll
                for (int ni = 0; ni < 4; ++ni) {
                    MMA_F16(acc[mi][2*ni],   ah[mi], bh[ni][0], bh[ni][1]);
                    MMA_F16(acc[mi][2*ni+1], ah[mi], bh[ni][2], bh[ni][3]);
                }
        }

        // ---- tile finished: epilogue (overlaps next pair's in-flight loads) ----
        if ((ci & (KITER - 1)) == KITER - 1) {
            int tile = bx + (ci >> 4) * grid;
            int tm = tile / ntN;
            int tn = tile - tm * ntN;
#pragma unroll
            for (int mi = 0; mi < 4; ++mi) {
                int gm = tm * BM + wm + mi * 16 + (lane >> 2);
#pragma unroll
                for (int ni = 0; ni < 8; ++ni) {
                    int gn = tn * BN + wn + ni * 8 + (lane & 3) * 2;
                    if constexpr (sizeof(OutT) == 4) {
                        float2 v0 = make_float2(acc[mi][ni][0], acc[mi][ni][1]);
                        float2 v1 = make_float2(acc[mi][ni][2], acc[mi][ni][3]);
                        *(float2*)((float*)C + (size_t)gm * ldc + gn) = v0;
                        *(float2*)((float*)C + (size_t)(gm + 8) * ldc + gn) = v1;
                    } else {
                        __half2 h0; h0.x = __float2half_rn(acc[mi][ni][0]); h0.y = __float2half_rn(acc[mi][ni][1]);
                        __half2 h1; h1.x = __float2half_rn(acc[mi][ni][2]); h1.y = __float2half_rn(acc[mi][ni][3]);
                        *(__half2*)((__half*)C + (size_t)gm * ldc + gn) = h0;
                        *(__half2*)((__half*)C + (size_t)(gm + 8) * ldc + gn) = h1;
                    }
                }
            }
#pragma unroll
            for (int i = 0; i < 4; ++i)
#pragma unroll
                for (int j = 0; j < 8; ++j)
#pragma unroll
                    for (int q = 0; q < 4; ++q) acc[i][j][q] = 0.f;
        }
    }
}

// ---------------- fused RoPE + 16x16 head-attn, 2 tokens per block ----------------
#define PAD 65
__global__ __launch_bounds__(256) void attn_kernel()
{
    __shared__ float q [2][HH][PAD];
    __shared__ float kk[2][HH][PAD];
    __shared__ float vv[2][HH][PAD];
    __shared__ float sc[2][HH][17];
    __shared__ float cs[2][32], sn[2][32];

    const int tok0 = blockIdx.x * 2;
    const int tid = threadIdx.x;

    if (tid < 64) {
        int tk = tid >> 5, d2 = tid & 31;
        int t = (tok0 + tk) & (TT - 1);
        cs[tk][d2] = g_cos[t*32 + d2];
        sn[tk][d2] = g_sin[t*32 + d2];
    }

    const float4* base = (const float4*)(g_qkv + (size_t)tok0 * QKVC);
#pragma unroll
    for (int r = 0; r < 3; ++r) {
        int id = r * 256 + tid;
        float4 raw = base[id];
        int tk = id >= 384;
        int f  = id - tk * 384;
        int s  = f >> 7;
        int h  = (f >> 3) & 15;
        int d0 = (f & 7) * 8;
        float* dst = (s == 0 ? &q[tk][h][d0] : s == 1 ? &kk[tk][h][d0] : &vv[tk][h][d0]);
        const __half2* hp = (const __half2*)&raw;
#pragma unroll
        for (int j = 0; j < 4; ++j) {
            float2 fv = __half22float2(hp[j]);
            dst[2*j]   = fv.x;
            dst[2*j+1] = fv.y;
        }
    }
    __syncthreads();

#pragma unroll
    for (int r = 0; r < 8; ++r) {
        int idx = tid + 256 * r;
        int tk = idx >> 10;
        int which = (idx >> 9) & 1;
        int h = (idx >> 5) & 15;
        int d2 = idx & 31;
        float c = cs[tk][d2], s = sn[tk][d2];
        float* buf = which ? &kk[tk][0][0] : &q[tk][0][0];
        float x1 = buf[h*PAD + 2*d2];
        float x2 = buf[h*PAD + 2*d2 + 1];
        buf[h*PAD + 2*d2]     = x1*c - x2*s;
        buf[h*PAD + 2*d2 + 1] = x2*c + x1*s;
    }
    __syncthreads();

#pragma unroll
    for (int r = 0; r < 2; ++r) {
        int idx = tid + 256 * r;
        int tk = idx >> 8;
        int hq = (idx >> 4) & 15, hk = idx & 15;
        float s = 0.f;
#pragma unroll
        for (int d = 0; d < DD; ++d) s = fmaf(q[tk][hq][d], kk[tk][hk][d], s);
        sc[tk][hq][hk] = s * 0.125f;
    }
    __syncthreads();

    if (tid < 32) {
        int tk = tid >> 4, row = tid & 15;
        float mx = -1e30f;
#pragma unroll
        for (int j = 0; j < 16; ++j) mx = fmaxf(mx, sc[tk][row][j]);
        float sum = 0.f;
#pragma unroll
        for (int j = 0; j < 16; ++j) { float e = expf(sc[tk][row][j] - mx); sc[tk][row][j] = e; sum += e; }
        float inv = 1.f / sum;
#pragma unroll
        for (int j = 0; j < 16; ++j) sc[tk][row][j] *= inv;
    }
    __syncthreads();

#pragma unroll
    for (int r = 0; r < 8; ++r) {
        int idx = tid + 256 * r;
        int tk = idx >> 10;
        int hq = (idx >> 6) & 15, d = idx & 63;
        float o = 0.f;
#pragma unroll
        for (int hk = 0; hk < 16; ++hk) o = fmaf(sc[tk][hq][hk], vv[tk][hk][d], o);
        int tg = tok0 + tk;
        int b = tg >> 13, t = tg & (TT - 1);
        size_t obase = ((size_t)b * TT + (t >> 4)) * (size_t)CC + (size_t)(t & 15) * DD;
        g_sh[obase + (size_t)hq * 512 * CC + d] = __float2half_rn(o);
    }
}

// ---------------------------------------------------------------------------
extern "C" void kernel_launch(void* const* d_in, const int* in_sizes, int n_in,
                              void* d_out, int out_size)
{
    const float* x    = (const float*)d_in[0];
    const float* Wqkv = (const float*)d_in[1];
    const float* Wout = (const float*)d_in[2];
    float* out = (float*)d_out;

    __half *qkv_p, *xh, *sh, *wqh, *woh;
    cudaGetSymbolAddress((void**)&qkv_p, g_qkv);
    cudaGetSymbolAddress((void**)&xh, g_xh);
    cudaGetSymbolAddress((void**)&sh, g_sh);
    cudaGetSymbolAddress((void**)&wqh, g_wqh);
    cudaGetSymbolAddress((void**)&woh, g_woh);

    int nsm = 148;
    cudaDeviceGetAttribute(&nsm, cudaDevAttrMultiProcessorCount, 0);

    cudaFuncSetAttribute(gemm_mma<__half>, cudaFuncAttributeMaxDynamicSharedMemorySize, GEMM_DYN);
    cudaFuncSetAttribute(gemm_mma<float>,  cudaFuncAttributeMaxDynamicSharedMemorySize, GEMM_DYN);

    rope_table_kernel<<<(TT*32 + 255) / 256, 256>>>();
    cvt_kernel<<<(MTOT*CC/4) / 1024, 256>>>((const float4*)x,    (__half2*)xh,  MTOT*CC/4);
    cvt_kernel<<<(QKVC*CC/4) / 1024, 256>>>((const float4*)Wqkv, (__half2*)wqh, QKVC*CC/4);
    cvt_kernel<<<(CC*CC/4)   / 1024, 256>>>((const float4*)Wout, (__half2*)woh, CC*CC/4);

    // GEMM1: qkv(fp16) = x @ Wqkv^T  (M=16384, N=3072, K=1024) — 1536 tiles
    {
        int ntiles = (QKVC / BN) * (MTOT / BM);
        int grid = ntiles < nsm ? ntiles : nsm;
        gemm_mma<__half><<<grid, 256, GEMM_DYN>>>(xh, wqh, qkv_p, QKVC, CC, QKVC / BN, ntiles);
    }

    // fused RoPE + head-attention + scramble (2 tokens/block)
    attn_kernel<<<MTOT / 2, 256>>>();

    // GEMM2: out = scr @ Wout^T (M=16384, N=1024, K=1024) — 512 tiles
    {
        int ntiles = (CC / BN) * (MTOT / BM);
        int grid = ntiles < nsm ? ntiles : nsm;
        gemm_mma<float><<<grid, 256, GEMM_DYN>>>(sh, woh, out, CC, CC, CC / BN, ntiles);
    }
}

// round 12
// speedup vs baseline: 4.6158x; 1.0112x over previous
#include <cuda_runtime.h>
#include <cuda_fp16.h>
#include <math.h>
#include <stdint.h>

#define BB 2
#define TT 8192
#define CC 1024
#define HH 16
#define DD 64
#define MTOT (BB*TT)        // 16384
#define QKVC (3*CC)         // 3072

// ---------------- device scratch ----------------
__device__ __half g_qkv[(size_t)MTOT * QKVC];      // 96 MB fp16
__device__ __half g_xh[(size_t)MTOT * CC];
__device__ __half g_sh[(size_t)MTOT * CC];
__device__ __half g_wqh[(size_t)QKVC * CC];
__device__ __half g_woh[(size_t)CC * CC];
__device__ float g_cos[TT * 32];
__device__ float g_sin[TT * 32];

// ---------------- PTX helpers ----------------
__device__ __forceinline__ uint32_t smem_u32(const void* p) {
    uint32_t a;
    asm("{ .reg .u64 t; cvta.to.shared.u64 t, %1; cvt.u32.u64 %0, t; }" : "=r"(a) : "l"(p));
    return a;
}
__device__ __forceinline__ void cp16(uint32_t s, const void* g) {
    asm volatile("cp.async.cg.shared.global [%0], [%1], 16;" :: "r"(s), "l"(g));
}
#define CP_COMMIT() asm volatile("cp.async.commit_group;" ::: "memory")
#define CP_WAIT(n)  asm volatile("cp.async.wait_group %0;" :: "n"(n) : "memory")

__device__ __forceinline__ void ldsm_x4(uint32_t* r, uint32_t addr) {
    asm volatile("ldmatrix.sync.aligned.m8n8.x4.shared.b16 {%0,%1,%2,%3}, [%4];"
                 : "=r"(r[0]), "=r"(r[1]), "=r"(r[2]), "=r"(r[3]) : "r"(addr));
}
#define MMA_F16(d, a, b0, b1) \
    asm volatile("mma.sync.aligned.m16n8k16.row.col.f32.f16.f16.f32 " \
                 "{%0,%1,%2,%3}, {%4,%5,%6,%7}, {%8,%9}, {%0,%1,%2,%3};" \
                 : "+f"((d)[0]), "+f"((d)[1]), "+f"((d)[2]), "+f"((d)[3]) \
                 : "r"((a)[0]), "r"((a)[1]), "r"((a)[2]), "r"((a)[3]), \
                   "r"(b0), "r"(b1))

// ---------------- small kernels ----------------
__global__ void rope_table_kernel() {
    int idx = blockIdx.x * blockDim.x + threadIdx.x;
    if (idx >= TT * 32) return;
    int t = idx >> 5, d2 = idx & 31;
    float invf = (float)pow(10000.0, -(double)d2 / 32.0);
    float ang = __fmul_rn((float)t, invf);
    g_cos[idx] = (float)cos((double)ang);
    g_sin[idx] = (float)sin((double)ang);
}

__global__ void cvt_kernel(const float4* __restrict__ in,
                           __half2* __restrict__ hi, int n4) {
    int base = blockIdx.x * 1024 + threadIdx.x;
    float4 v[4];
#pragma unroll
    for (int k = 0; k < 4; ++k) v[k] = in[base + k * 256];
#pragma unroll
    for (int k = 0; k < 4; ++k) {
        int f = base + k * 256;
        __half2 a = __floats2half2_rn(v[k].x, v[k].y);
        __half2 b = __floats2half2_rn(v[k].z, v[k].w);
        uint2 pk; pk.x = *(uint32_t*)&a; pk.y = *(uint32_t*)&b;
        ((uint2*)hi)[f] = pk;
    }
}

// ---------------- persistent fp16 GEMM (NT): C[m,n] = sum_k A[m,k]*B[n,k] ----------------
// CTA tile 128x256, warp tile 64x64 (2x4 warps), BK=64, 4-stage cp.async ring.
// Pair processing: one CP_WAIT + one barrier per TWO K-iters, with fragment
// double-buffering across the 8 ks-steps so ldsm latency hides under MMA issue.
#define BM 128
#define BN 256
#define BKQ 64
#define KITER 16            // K(=1024)/BKQ
#define T_A 0
#define T_B (16*1024)
#define STG  (48*1024)
#define NSTAGE 4
#define GEMM_DYN (NSTAGE*STG + 1024)

extern __shared__ char dynsmem[];

template <typename OutT>
__global__ __launch_bounds__(256, 1) void gemm_mma(
    const __half* __restrict__ Ah,
    const __half* __restrict__ Bh,
    OutT* __restrict__ C, int ldc, int K, int ntN, int ntiles)
{
    const int tid  = threadIdx.x;
    const int wid  = tid >> 5;
    const int lane = tid & 31;
    const int wm = (wid >> 2) * 64;
    const int wn = (wid & 3) * 64;
    const int bx = blockIdx.x;
    const int grid = gridDim.x;

    const int my_nt = (ntiles - 1 - bx) / grid + 1;
    const int my_iters = my_nt * KITER;       // always even (KITER=16)

    uint32_t sbase = (smem_u32(dynsmem) + 1023u) & ~1023u;

    // ---- loader setup ----
    const int lrow = tid >> 1;
    const int lc4  = (tid & 1) * 4;
    uint32_t soffA[4], soffB1[4];
#pragma unroll
    for (int c = 0; c < 4; ++c) {
        uint32_t offA = (uint32_t)lrow * 128 + (uint32_t)(lc4 + c) * 16;
        soffA[c] = offA ^ ((offA >> 3) & 0x70);
        uint32_t offB1 = (uint32_t)(lrow + 128) * 128 + (uint32_t)(lc4 + c) * 16;
        soffB1[c] = offB1 ^ ((offB1 >> 3) & 0x70);
    }
    const int gcol = lc4 * 8;

    // incremental load cursor
    int ld_tile = bx;
    int ld_tm = ld_tile / ntN;
    int ld_tn = ld_tile - ld_tm * ntN;
    int ld_kk = 0;
    int ld_stage = 0;

    auto load_stage = [&]() {
        const __half* gA  = Ah + (size_t)(ld_tm * BM + lrow) * K + ld_kk * BKQ + gcol;
        const __half* gB0 = Bh + (size_t)(ld_tn * BN + lrow) * K + ld_kk * BKQ + gcol;
        const __half* gB1 = gB0 + (size_t)128 * K;
        uint32_t st = sbase + (uint32_t)(ld_stage & (NSTAGE - 1)) * STG;
#pragma unroll
        for (int c = 0; c < 4; ++c) {
            cp16(st + T_A + soffA[c],  gA  + c * 8);
            cp16(st + T_B + soffA[c],  gB0 + c * 8);
            cp16(st + T_B + soffB1[c], gB1 + c * 8);
        }
        CP_COMMIT();
        ++ld_stage;
        if (++ld_kk == KITER) {
            ld_kk = 0;
            ld_tile += grid;
            ld_tm = ld_tile / ntN;
            ld_tn = ld_tile - ld_tm * ntN;
        }
    };

    // ---- ldmatrix address precompute (tile-invariant) ----
    uint32_t a_rt[4], a_xr[4];
#pragma unroll
    for (int ti = 0; ti < 4; ++ti) {
        int r = wm + ti * 16 + (lane & 15);
        a_rt[ti] = (uint32_t)r * 128;
        a_xr[ti] = (uint32_t)(r & 7) << 4;
    }
    const uint32_t a_cb = (uint32_t)(lane >> 4) * 16;
    uint32_t b_rt[4], b_xr[4];
#pragma unroll
    for (int ni = 0; ni < 4; ++ni) {
        int r = wn + ni * 16 + (lane & 7) + (lane >> 4) * 8;
        b_rt[ni] = (uint32_t)r * 128;
        b_xr[ni] = (uint32_t)(r & 7) << 4;
    }
    const uint32_t b_cb = (uint32_t)((lane >> 3) & 1) * 16;

    float acc[4][8][4];
#pragma unroll
    for (int i = 0; i < 4; ++i)
#pragma unroll
        for (int j = 0; j < 8; ++j)
#pragma unroll
            for (int q = 0; q < 4; ++q) acc[i][j][q] = 0.f;

    // ---- prologue: two stages in flight ----
    load_stage();
    load_stage();

    // ---- mainloop: one wait+barrier per pair; 8 ks-steps, frag double-buffer ----
    for (int cp = 0; cp < my_iters; cp += 2) {
        CP_WAIT(0);                      // stages cp, cp+1 resident
        __syncthreads();                 // everyone done reading stages cp+2&3, cp+3&3
        if (cp + 2 < my_iters) load_stage();
        if (cp + 3 < my_iters) load_stage();

        const uint32_t base0 = sbase + (uint32_t)((cp)     & (NSTAGE - 1)) * STG;
        const uint32_t base1 = sbase + (uint32_t)((cp + 1) & (NSTAGE - 1)) * STG;

        uint32_t ah[2][4][4], bh[2][4][4];
        // prefetch ks-step 0
#pragma unroll
        for (int ni = 0; ni < 4; ++ni)
            ldsm_x4(bh[0][ni], base0 + T_B + b_rt[ni] + (b_cb ^ b_xr[ni]));
#pragma unroll
        for (int ti = 0; ti < 4; ++ti)
            ldsm_x4(ah[0][ti], base0 + T_A + a_rt[ti] + (a_cb ^ a_xr[ti]));

#pragma unroll
        for (int s = 0; s < 8; ++s) {
            const int cur = s & 1;
            const int nx  = cur ^ 1;
            if (s < 7) {   // issue ldsm for step s+1 ahead of this step's MMAs
                const uint32_t bb = (s + 1 < 4) ? base0 : base1;
                const uint32_t kb = (uint32_t)((s + 1) & 3) * 32;
#pragma unroll
                for (int ni = 0; ni < 4; ++ni)
                    ldsm_x4(bh[nx][ni], bb + T_B + b_rt[ni] + ((b_cb + kb) ^ b_xr[ni]));
#pragma unroll
                for (int ti = 0; ti < 4; ++ti)
                    ldsm_x4(ah[nx][ti], bb + T_A + a_rt[ti] + ((a_cb + kb) ^ a_xr[ti]));
            }
#pragma unroll
            for (int mi = 0; mi < 4; ++mi)
#pragma unroll
                for (int ni = 0; ni < 4; ++ni) {
                    MMA_F16(acc[mi][2*ni],   ah[cur][mi], bh[cur][ni][0], bh[cur][ni][1]);
                    MMA_F16(acc[mi][2*ni+1], ah[cur][mi], bh[cur][ni][2], bh[cur][ni][3]);
                }
        }

        // ---- tile finished at cp+1? epilogue (overlaps next pair's loads) ----
        if (((cp + 1) & (KITER - 1)) == KITER - 1) {
            int tile = bx + ((cp + 1) >> 4) * grid;
            int tm = tile / ntN;
            int tn = tile - tm * ntN;
#pragma unroll
            for (int mi = 0; mi < 4; ++mi) {
                int gm = tm * BM + wm + mi * 16 + (lane >> 2);
#pragma unroll
                for (int ni = 0; ni < 8; ++ni) {
                    int gn = tn * BN + wn + ni * 8 + (lane & 3) * 2;
                    if constexpr (sizeof(OutT) == 4) {
                        float2 v0 = make_float2(acc[mi][ni][0], acc[mi][ni][1]);
                        float2 v1 = make_float2(acc[mi][ni][2], acc[mi][ni][3]);
                        *(float2*)((float*)C + (size_t)gm * ldc + gn) = v0;
                        *(float2*)((float*)C + (size_t)(gm + 8) * ldc + gn) = v1;
                    } else {
                        __half2 h0; h0.x = __float2half_rn(acc[mi][ni][0]); h0.y = __float2half_rn(acc[mi][ni][1]);
                        __half2 h1; h1.x = __float2half_rn(acc[mi][ni][2]); h1.y = __float2half_rn(acc[mi][ni][3]);
                        *(__half2*)((__half*)C + (size_t)gm * ldc + gn) = h0;
                        *(__half2*)((__half*)C + (size_t)(gm + 8) * ldc + gn) = h1;
                    }
                }
            }
#pragma unroll
            for (int i = 0; i < 4; ++i)
#pragma unroll
                for (int j = 0; j < 8; ++j)
#pragma unroll
                    for (int q = 0; q < 4; ++q) acc[i][j][q] = 0.f;
        }
    }
}

// ---------------- fused RoPE + 16x16 head-attn, 2 tokens per block ----------------
#define PAD 65
__global__ __launch_bounds__(256) void attn_kernel()
{
    __shared__ float q [2][HH][PAD];
    __shared__ float kk[2][HH][PAD];
    __shared__ float vv[2][HH][PAD];
    __shared__ float sc[2][HH][17];
    __shared__ float cs[2][32], sn[2][32];

    const int tok0 = blockIdx.x * 2;
    const int tid = threadIdx.x;

    if (tid < 64) {
        int tk = tid >> 5, d2 = tid & 31;
        int t = (tok0 + tk) & (TT - 1);
        cs[tk][d2] = g_cos[t*32 + d2];
        sn[tk][d2] = g_sin[t*32 + d2];
    }

    const float4* base = (const float4*)(g_qkv + (size_t)tok0 * QKVC);
#pragma unroll
    for (int r = 0; r < 3; ++r) {
        int id = r * 256 + tid;
        float4 raw = base[id];
        int tk = id >= 384;
        int f  = id - tk * 384;
        int s  = f >> 7;
        int h  = (f >> 3) & 15;
        int d0 = (f & 7) * 8;
        float* dst = (s == 0 ? &q[tk][h][d0] : s == 1 ? &kk[tk][h][d0] : &vv[tk][h][d0]);
        const __half2* hp = (const __half2*)&raw;
#pragma unroll
        for (int j = 0; j < 4; ++j) {
            float2 fv = __half22float2(hp[j]);
            dst[2*j]   = fv.x;
            dst[2*j+1] = fv.y;
        }
    }
    __syncthreads();

#pragma unroll
    for (int r = 0; r < 8; ++r) {
        int idx = tid + 256 * r;
        int tk = idx >> 10;
        int which = (idx >> 9) & 1;
        int h = (idx >> 5) & 15;
        int d2 = idx & 31;
        float c = cs[tk][d2], s = sn[tk][d2];
        float* buf = which ? &kk[tk][0][0] : &q[tk][0][0];
        float x1 = buf[h*PAD + 2*d2];
        float x2 = buf[h*PAD + 2*d2 + 1];
        buf[h*PAD + 2*d2]     = x1*c - x2*s;
        buf[h*PAD + 2*d2 + 1] = x2*c + x1*s;
    }
    __syncthreads();

#pragma unroll
    for (int r = 0; r < 2; ++r) {
        int idx = tid + 256 * r;
        int tk = idx >> 8;
        int hq = (idx >> 4) & 15, hk = idx & 15;
        float s = 0.f;
#pragma unroll
        for (int d = 0; d < DD; ++d) s = fmaf(q[tk][hq][d], kk[tk][hk][d], s);
        sc[tk][hq][hk] = s * 0.125f;
    }
    __syncthreads();

    if (tid < 32) {
        int tk = tid >> 4, row = tid & 15;
        float mx = -1e30f;
#pragma unroll
        for (int j = 0; j < 16; ++j) mx = fmaxf(mx, sc[tk][row][j]);
        float sum = 0.f;
#pragma unroll
        for (int j = 0; j < 16; ++j) { float e = expf(sc[tk][row][j] - mx); sc[tk][row][j] = e; sum += e; }
        float inv = 1.f / sum;
#pragma unroll
        for (int j = 0; j < 16; ++j) sc[tk][row][j] *= inv;
    }
    __syncthreads();

#pragma unroll
    for (int r = 0; r < 8; ++r) {
        int idx = tid + 256 * r;
        int tk = idx >> 10;
        int hq = (idx >> 6) & 15, d = idx & 63;
        float o = 0.f;
#pragma unroll
        for (int hk = 0; hk < 16; ++hk) o = fmaf(sc[tk][hq][hk], vv[tk][hk][d], o);
        int tg = tok0 + tk;
        int b = tg >> 13, t = tg & (TT - 1);
        size_t obase = ((size_t)b * TT + (t >> 4)) * (size_t)CC + (size_t)(t & 15) * DD;
        g_sh[obase + (size_t)hq * 512 * CC + d] = __float2half_rn(o);
    }
}

// ---------------------------------------------------------------------------
extern "C" void kernel_launch(void* const* d_in, const int* in_sizes, int n_in,
                              void* d_out, int out_size)
{
    const float* x    = (const float*)d_in[0];
    const float* Wqkv = (const float*)d_in[1];
    const float* Wout = (const float*)d_in[2];
    float* out = (float*)d_out;

    __half *qkv_p, *xh, *sh, *wqh, *woh;
    cudaGetSymbolAddress((void**)&qkv_p, g_qkv);
    cudaGetSymbolAddress((void**)&xh, g_xh);
    cudaGetSymbolAddress((void**)&sh, g_sh);
    cudaGetSymbolAddress((void**)&wqh, g_wqh);
    cudaGetSymbolAddress((void**)&woh, g_woh);

    int nsm = 148;
    cudaDeviceGetAttribute(&nsm, cudaDevAttrMultiProcessorCount, 0);

    cudaFuncSetAttribute(gemm_mma<__half>, cudaFuncAttributeMaxDynamicSharedMemorySize, GEMM_DYN);
    cudaFuncSetAttribute(gemm_mma<float>,  cudaFuncAttributeMaxDynamicSharedMemorySize, GEMM_DYN);

    rope_table_kernel<<<(TT*32 + 255) / 256, 256>>>();
    cvt_kernel<<<(MTOT*CC/4) / 1024, 256>>>((const float4*)x,    (__half2*)xh,  MTOT*CC/4);
    cvt_kernel<<<(QKVC*CC/4) / 1024, 256>>>((const float4*)Wqkv, (__half2*)wqh, QKVC*CC/4);
    cvt_kernel<<<(CC*CC/4)   / 1024, 256>>>((const float4*)Wout, (__half2*)woh, CC*CC/4);

    // GEMM1: qkv(fp16) = x @ Wqkv^T  (M=16384, N=3072, K=1024) — 1536 tiles
    {
        int ntiles = (QKVC / BN) * (MTOT / BM);
        int grid = ntiles < nsm ? ntiles : nsm;
        gemm_mma<__half><<<grid, 256, GEMM_DYN>>>(xh, wqh, qkv_p, QKVC, CC, QKVC / BN, ntiles);
    }

    // fused RoPE + head-attention + scramble (2 tokens/block)
    attn_kernel<<<MTOT / 2, 256>>>();

    // GEMM2: out = scr @ Wout^T (M=16384, N=1024, K=1024) — 512 tiles
    {
        int ntiles = (CC / BN) * (MTOT / BM);
        int grid = ntiles < nsm ? ntiles : nsm;
        gemm_mma<float><<<grid, 256, GEMM_DYN>>>(sh, woh, out, CC, CC, CC / BN, ntiles);
    }
}